// round 15
// baseline (speedup 1.0000x reference)
#include <cuda_runtime.h>
#include <cuda_bf16.h>
#include <math.h>

// ---------------- problem constants ----------------
namespace {
constexpr int NB = 128;                       // batch
constexpr int C0 = 30, H0 = 15, W0 = 15;      // input
constexpr int C1 = 256, W1 = 13, P1 = 169;    // after conv1 (13x13)
constexpr int C2 = 256, W2 = 11, P2 = 121;    // after conv2 (11x11)
constexpr int NCAPS = 3872, IND = 8, NCLS = 16;
constexpr int NFLAT = C2 * P2;                // 30976
constexpr int NCHUNKS = 88, NPC = 44;         // 88*44 = 3872
constexpr int DEC1 = 328, DEC2 = 192, DEC3 = 6750;
constexpr int K2 = 2304, KC = 16, NKC = K2 / KC;   // conv2 GEMM K, chunks of 16
constexpr int KR = NCAPS * IND;               // 30976 routing GEMM K
constexpr int KR_SPLIT = KR / NCHUNKS;        // 352 k per split (22 chunks of 16)
}

// ---------------- scratch (static device memory, no allocs) ----------------
__device__ __align__(16) float g_h[NB * C1 * P1];            // conv1 out
__device__ __align__(16) float g_pbuf[NB * NFLAT];           // conv2 out
__device__ __align__(16) float g_caps[KR * NB];              // caps_t[n*8+j][b] fp32
__device__ __align__(16) unsigned g_caps_pk[KR * NB];        // caps bf16 (hi|lo<<16)
__device__ __align__(16) float g_wt[NCAPS * 2048];           // caps_w [n][o][i][j]
__device__ __align__(16) unsigned short g_wrph[(size_t)KR * 256];  // route w bf16 hi, k-paired
__device__ __align__(16) unsigned short g_wrpl[(size_t)KR * 256];  // route w bf16 lo, k-paired
__device__ __align__(16) float g_w1t[270 * 256];             // conv1 w [r][co]
__device__ __align__(16) unsigned short g_w2ph[K2 * 256];    // conv2 w bf16 hi, k-paired
__device__ __align__(16) unsigned short g_w2pl[K2 * 256];    // conv2 w bf16 lo, k-paired
__device__ __align__(16) unsigned g_hpk[NB * C1 * P1];       // relu(bn(h)) packed (hi|lo<<16)
__device__ __align__(16) float g_spart[(size_t)NCHUNKS * NB * 256];
__device__ __align__(16) float g_out_sum[NB * 256];
__device__ float g_masked[NB * 256];
__device__ float g_r1[NB * DEC1];
__device__ float g_r2[NB * DEC2];

// ---------------- fused transpose of both conv weights ----------------
__global__ void k_tr_both(const float* __restrict__ c1w, const float* __restrict__ c2w) {
  const int c1 = blockIdx.x < 9;
  const float* __restrict__ src = c1 ? c1w : c2w;
  const int M = 256;
  const int N = c1 ? 270 : 2304;
  const int bx = c1 ? blockIdx.x : blockIdx.x - 9;
  __shared__ float t[32][33];
  const int tx = threadIdx.x;
  const int x = bx * 32 + tx;
  const int y0 = blockIdx.y * 32;
  for (int j = threadIdx.y; j < 32; j += 8) {
    int y = y0 + j;
    if (x < N && y < M) t[j][tx] = src[(size_t)y * N + x];
  }
  __syncthreads();
  const int xo = y0 + tx;   // co (M dim)
  const int yo0 = bx * 32;
  for (int j = threadIdx.y; j < 32; j += 8) {
    int yo = yo0 + j;       // k (N dim)
    if (xo < M && yo < N) {
      float v = t[tx][j];
      if (c1) {
        g_w1t[(size_t)yo * M + xo] = v;
      } else {
        __nv_bfloat16 bh = __float2bfloat16(v);
        float vh = __bfloat162float(bh);
        __nv_bfloat16 bl = __float2bfloat16(v - vh);
        size_t idx = (size_t)(yo >> 1) * 512 + 2 * xo + (yo & 1);
        g_w2ph[idx] = __bfloat16_as_ushort(bh);
        g_w2pl[idx] = __bfloat16_as_ushort(bl);
      }
    }
  }
}

// ---------------- caps_w transpose + route-GEMM weight planes ----------------
__global__ void k_transpose_w(const float* __restrict__ cw) {
  int idx = blockIdx.x * 256 + threadIdx.x;       // over 16*3872*128
  if (idx >= NCLS * NCAPS * 128) return;
  int o = idx / (NCAPS * 128);
  int rem = idx - o * (NCAPS * 128);
  int n = rem >> 7;
  int ij = rem & 127;
  float v = cw[idx];
  g_wt[n * 2048 + o * 128 + ij] = v;
  int i = ij >> 3, j = ij & 7;
  int nj = n * 8 + j, oi = o * 16 + i;
  __nv_bfloat16 bh = __float2bfloat16(v);
  float vh = __bfloat162float(bh);
  __nv_bfloat16 bl = __float2bfloat16(v - vh);
  size_t widx = (size_t)(nj >> 1) * 512 + 2 * oi + (nj & 1);
  g_wrph[widx] = __bfloat16_as_ushort(bh);
  g_wrpl[widx] = __bfloat16_as_ushort(bl);
}

// ---------------- conv1: 30->256, 3x3 valid, 15x15 -> 13x13 ----------------
__global__ void __launch_bounds__(256) k_conv1(const float* __restrict__ x,
                                               const float* __restrict__ bias) {
  __shared__ __align__(16) float xs[C0 * H0 * W0];   // 27000 B
  __shared__ __align__(16) float ws[135 * 32];       // 17280 B: [r][co_local]
  const int b = blockIdx.y, cot = blockIdx.x;     // 8 co-tiles of 32
  const int tid = threadIdx.x;
  const float* xb = x + (size_t)b * (C0 * H0 * W0);
  for (int i = tid; i < C0 * H0 * W0; i += 256) xs[i] = xb[i];
  const int p0 = tid & 63, cg = tid >> 6;         // 4 co-groups of 8 co
  int ph[3], pw[3];
  bool pv[3];
#pragma unroll
  for (int k = 0; k < 3; k++) {
    int p = p0 + 64 * k;
    pv[k] = p < P1;
    int pp = pv[k] ? p : 0;
    ph[k] = pp / W1; pw[k] = pp - (pp / W1) * W1;
  }
  float acc[8][3];
#pragma unroll
  for (int c = 0; c < 8; c++)
#pragma unroll
    for (int k = 0; k < 3; k++) acc[c][k] = 0.f;
  for (int half = 0; half < 2; half++) {          // ci chunks of 15
    __syncthreads();
    for (int i = tid; i < 135 * 32; i += 256) {
      int r = i >> 5, col = i & 31;
      ws[i] = g_w1t[(half * 135 + r) * 256 + cot * 32 + col];
    }
    __syncthreads();
    for (int cil = 0; cil < 15; cil++) {
      const float* xc = xs + (half * 15 + cil) * (H0 * W0);
#pragma unroll
      for (int kh = 0; kh < 3; kh++) {
#pragma unroll
        for (int kw = 0; kw < 3; kw++) {
          const float* wr = ws + (cil * 9 + kh * 3 + kw) * 32 + cg * 8;
          float4 wa = *(const float4*)wr;
          float4 wb = *(const float4*)(wr + 4);
#pragma unroll
          for (int k = 0; k < 3; k++) {
            float xv = xc[(ph[k] + kh) * W0 + pw[k] + kw];
            acc[0][k] += wa.x * xv;
            acc[1][k] += wa.y * xv;
            acc[2][k] += wa.z * xv;
            acc[3][k] += wa.w * xv;
            acc[4][k] += wb.x * xv;
            acc[5][k] += wb.y * xv;
            acc[6][k] += wb.z * xv;
            acc[7][k] += wb.w * xv;
          }
        }
      }
    }
  }
#pragma unroll
  for (int c = 0; c < 8; c++) {
    int co = cot * 32 + cg * 8 + c;
    float bs = bias[co];
#pragma unroll
    for (int k = 0; k < 3; k++)
      if (pv[k]) g_h[((size_t)b * C1 + co) * P1 + p0 + 64 * k] = acc[c][k] + bs;
  }
}

// ---------------- batchnorm stats + fused BN+relu+bf16-split pack ----------------
__global__ void k_bnstats(const float* __restrict__ gamma, const float* __restrict__ beta) {
  const int c = blockIdx.x, tid = threadIdx.x;
  float s = 0.f, s2 = 0.f;
  for (int i = tid; i < NB * P1; i += 256) {
    int b = i / P1, p = i - (i / P1) * P1;
    float v = g_h[((size_t)b * C1 + c) * P1 + p];
    s += v; s2 += v * v;
  }
  __shared__ float rs[256], rq[256];
  __shared__ float ssc, ssh;
  rs[tid] = s; rq[tid] = s2;
  __syncthreads();
  for (int st = 128; st > 0; st >>= 1) {
    if (tid < st) { rs[tid] += rs[tid + st]; rq[tid] += rq[tid + st]; }
    __syncthreads();
  }
  if (tid == 0) {
    const float inv_n = 1.f / (float)(NB * P1);
    float mean = rs[0] * inv_n;
    float var = fmaxf(rq[0] * inv_n - mean * mean, 0.f);
    float sc = gamma[c] * rsqrtf(var + 1e-5f);
    ssc = sc;
    ssh = beta[c] - mean * sc;
  }
  __syncthreads();
  const float sc = ssc, sh = ssh;
  for (int i = tid; i < NB * P1; i += 256) {
    int b = i / P1, p = i - (i / P1) * P1;
    size_t idx = ((size_t)b * C1 + c) * P1 + p;
    float v = g_h[idx] * sc + sh;
    v = v > 0.f ? v : 0.f;
    __nv_bfloat16 bh = __float2bfloat16(v);
    float vh = __bfloat162float(bh);
    __nv_bfloat16 bl = __float2bfloat16(v - vh);
    g_hpk[idx] = (unsigned)__bfloat16_as_ushort(bh) |
                 ((unsigned)__bfloat16_as_ushort(bl) << 16);
  }
}

// ---------------- conv2 as implicit GEMM on tensor cores (3-term bf16 k16) ----------------
__device__ __forceinline__ void mma16(float* c, const unsigned* a, const unsigned* b) {
  asm volatile(
      "mma.sync.aligned.m16n8k16.row.col.f32.bf16.bf16.f32 "
      "{%0,%1,%2,%3},{%4,%5,%6,%7},{%8,%9},{%0,%1,%2,%3};"
      : "+f"(c[0]), "+f"(c[1]), "+f"(c[2]), "+f"(c[3])
      : "r"(a[0]), "r"(a[1]), "r"(a[2]), "r"(a[3]), "r"(b[0]), "r"(b[1]));
}

// grid (4, NB): blockIdx.x = co quarter (64), blockIdx.y = batch image
// block 256 thr = 8 warps as 2(M=32) x 4(N=32); K chunks of 16, dbl-buffered; 3 blocks/SM
__global__ void __launch_bounds__(256, 3) k_conv2_mma(const float* __restrict__ b2) {
  __shared__ __align__(16) unsigned As_h[2][8 * 72];
  __shared__ __align__(16) unsigned As_l[2][8 * 72];
  __shared__ __align__(16) unsigned Bs_h[2][8 * 136];
  __shared__ __align__(16) unsigned Bs_l[2][8 * 136];
  __shared__ int offs_s[K2];
  __shared__ int posoff_s[128];
  const int b = blockIdx.y, cbt = blockIdx.x;
  const int tid = threadIdx.x;
  for (int i = tid; i < K2; i += 256) {
    int ci = i / 9, r = i - 9 * ci;
    int kh = r / 3, kw = r - 3 * kh;
    offs_s[i] = ci * P1 + kh * W1 + kw;
  }
  if (tid < 128) posoff_s[tid] = (tid / 11) * W1 + (tid - (tid / 11) * 11);
  const int lane = tid & 31, gid = lane >> 2, tg = lane & 3;
  const int w = tid >> 5, wm = w >> 2, wn = w & 3;
  const int cb = wm * 32, pb = wn * 32;
  float acc[2][4][4];
#pragma unroll
  for (int mt = 0; mt < 2; mt++)
#pragma unroll
    for (int nt = 0; nt < 4; nt++)
#pragma unroll
      for (int q = 0; q < 4; q++) acc[mt][nt][q] = 0.f;
  const unsigned* __restrict__ hpk = g_hpk + (size_t)b * C1 * P1;
  const unsigned* __restrict__ wAh = (const unsigned*)g_w2ph;
  const unsigned* __restrict__ wAl = (const unsigned*)g_w2pl;
  const int skkA = tid >> 6, scolA = tid & 63;     // A staging: 2 elems/thread
  const int skkB = tid >> 7, scolB = tid & 127;    // B staging: 4 elems/thread
  const int coA = cbt * 64 + scolA;
  unsigned pa_h[2], pa_l[2], pb_h[4], pb_l[4];
#define PREFETCH(kc_)                                                         \
  {                                                                           \
    _Pragma("unroll") for (int t = 0; t < 2; t++) {                           \
      int p = skkA + 4 * t;                                                   \
      int k2g = (kc_) * 8 + p;                                                \
      pa_h[t] = wAh[(size_t)k2g * 256 + coA];                                 \
      pa_l[t] = wAl[(size_t)k2g * 256 + coA];                                 \
    }                                                                         \
    _Pragma("unroll") for (int t = 0; t < 4; t++) {                           \
      int p = skkB + 2 * t;                                                   \
      unsigned e0 = 0, e1 = 0;                                                \
      if (scolB < 121) {                                                      \
        int po = posoff_s[scolB];                                             \
        int kg = (kc_) * KC + 2 * p;                                          \
        e0 = hpk[offs_s[kg] + po];                                            \
        e1 = hpk[offs_s[kg + 1] + po];                                        \
      }                                                                       \
      pb_h[t] = __byte_perm(e0, e1, 0x5410);                                  \
      pb_l[t] = __byte_perm(e0, e1, 0x7632);                                  \
    }                                                                         \
  }
#define STAGE(buf_)                                                           \
  {                                                                           \
    _Pragma("unroll") for (int t = 0; t < 2; t++) {                           \
      int p = skkA + 4 * t;                                                   \
      As_h[buf_][p * 72 + scolA] = pa_h[t];                                   \
      As_l[buf_][p * 72 + scolA] = pa_l[t];                                   \
    }                                                                         \
    _Pragma("unroll") for (int t = 0; t < 4; t++) {                           \
      int p = skkB + 2 * t;                                                   \
      Bs_h[buf_][p * 136 + scolB] = pb_h[t];                                  \
      Bs_l[buf_][p * 136 + scolB] = pb_l[t];                                  \
    }                                                                         \
  }
  __syncthreads();
  PREFETCH(0);
  STAGE(0);
  __syncthreads();
  for (int kc = 0; kc < NKC; kc++) {
    if (kc + 1 < NKC) PREFETCH(kc + 1);
    const unsigned* Ah = As_h[kc & 1];
    const unsigned* Al = As_l[kc & 1];
    const unsigned* Bh = Bs_h[kc & 1];
    const unsigned* Bl = Bs_l[kc & 1];
    unsigned bh[4][2], bl[4][2];
#pragma unroll
    for (int nt = 0; nt < 4; nt++) {
      int col = pb + nt * 8 + gid;
      bh[nt][0] = Bh[tg * 136 + col];
      bh[nt][1] = Bh[(tg + 4) * 136 + col];
      bl[nt][0] = Bl[tg * 136 + col];
      bl[nt][1] = Bl[(tg + 4) * 136 + col];
    }
#pragma unroll
    for (int mt = 0; mt < 2; mt++) {
      int row = cb + mt * 16 + gid;
      unsigned ah[4] = {Ah[tg * 72 + row], Ah[tg * 72 + row + 8],
                        Ah[(tg + 4) * 72 + row], Ah[(tg + 4) * 72 + row + 8]};
      unsigned al[4] = {Al[tg * 72 + row], Al[tg * 72 + row + 8],
                        Al[(tg + 4) * 72 + row], Al[(tg + 4) * 72 + row + 8]};
#pragma unroll
      for (int nt = 0; nt < 4; nt++) {
        mma16(acc[mt][nt], ah, bh[nt]);
        mma16(acc[mt][nt], ah, bl[nt]);
        mma16(acc[mt][nt], al, bh[nt]);
      }
    }
    if (kc + 1 < NKC) STAGE((kc + 1) & 1);
    __syncthreads();
  }
  float* outb = g_pbuf + (size_t)b * NFLAT;
#pragma unroll
  for (int mt = 0; mt < 2; mt++) {
    int co = cbt * 64 + cb + mt * 16 + gid;
    float bs0 = b2[co], bs1 = b2[co + 8];
#pragma unroll
    for (int nt = 0; nt < 4; nt++) {
      int p = pb + nt * 8 + 2 * tg;
      if (p < P2) {
        outb[co * P2 + p] = acc[mt][nt][0] + bs0;
        outb[(co + 8) * P2 + p] = acc[mt][nt][2] + bs1;
      }
      if (p + 1 < P2) {
        outb[co * P2 + p + 1] = acc[mt][nt][1] + bs0;
        outb[(co + 8) * P2 + p + 1] = acc[mt][nt][3] + bs1;
      }
    }
  }
#undef PREFETCH
#undef STAGE
}

// ---------------- primary capsule squash + transpose + bf16 pack ----------------
__global__ void k_squash(void) {
  const int n = blockIdx.x, b = threadIdx.x;
  const float4* src = (const float4*)(g_pbuf + (size_t)b * NFLAT + n * IND);
  float4 a0 = src[0], a1 = src[1];
  float v[8] = {a0.x, a0.y, a0.z, a0.w, a1.x, a1.y, a1.z, a1.w};
  float ss = 0.f;
#pragma unroll
  for (int j = 0; j < 8; j++) ss += v[j] * v[j];
  float nrm = sqrtf(ss);
  float sc = ss / (1.f + ss) / (nrm + 1e-8f);
#pragma unroll
  for (int j = 0; j < 8; j++) {
    float cv = v[j] * sc;
    size_t idx = ((size_t)n * IND + j) * NB + b;
    g_caps[idx] = cv;
    __nv_bfloat16 bh = __float2bfloat16(cv);
    float vh = __bfloat162float(bh);
    __nv_bfloat16 bl = __float2bfloat16(cv - vh);
    g_caps_pk[idx] = (unsigned)__bfloat16_as_ushort(bh) |
                     ((unsigned)__bfloat16_as_ushort(bl) << 16);
  }
}

// ---------------- routing pass0 as GEMM (uniform coupling 1/16) ----------------
// grid (4 oi-quarters, 88 splits); block = 8 warps (2M x 4N), M=64 oi, N=128 b; 3 blocks/SM
__global__ void __launch_bounds__(256, 3) k_route0_mma() {
  __shared__ __align__(16) unsigned As_h[2][8 * 72];
  __shared__ __align__(16) unsigned As_l[2][8 * 72];
  __shared__ __align__(16) unsigned Bs_h[2][8 * 136];
  __shared__ __align__(16) unsigned Bs_l[2][8 * 136];
  const int quarter = blockIdx.x, split = blockIdx.y;
  const int tid = threadIdx.x;
  const int lane = tid & 31, gid = lane >> 2, tg = lane & 3;
  const int w = tid >> 5, wm = w >> 2, wn = w & 3;
  const int cb = wm * 32, pb = wn * 32;
  float acc[2][4][4];
#pragma unroll
  for (int mt = 0; mt < 2; mt++)
#pragma unroll
    for (int nt = 0; nt < 4; nt++)
#pragma unroll
      for (int q = 0; q < 4; q++) acc[mt][nt][q] = 0.f;
  const unsigned* __restrict__ wAh = (const unsigned*)g_wrph;  // u32 idx = pair*256 + oi
  const unsigned* __restrict__ wAl = (const unsigned*)g_wrpl;
  const int skkA = tid >> 6, scolA = tid & 63;
  const int skkB = tid >> 7, scolB = tid & 127;
  const int oiA = quarter * 64 + scolA;
  const int kp0 = split * (KR_SPLIT / 2);    // 176 pairs per split
  unsigned pa_h[2], pa_l[2], pb_h[4], pb_l[4];
#define PREFETCH(kc_)                                                         \
  {                                                                           \
    _Pragma("unroll") for (int t = 0; t < 2; t++) {                           \
      int p = skkA + 4 * t;                                                   \
      int pg = kp0 + (kc_) * 8 + p;                                           \
      pa_h[t] = wAh[(size_t)pg * 256 + oiA];                                  \
      pa_l[t] = wAl[(size_t)pg * 256 + oiA];                                  \
    }                                                                         \
    _Pragma("unroll") for (int t = 0; t < 4; t++) {                           \
      int p = skkB + 2 * t;                                                   \
      int pg = kp0 + (kc_) * 8 + p;                                           \
      unsigned e0 = g_caps_pk[(size_t)(2 * pg) * NB + scolB];                 \
      unsigned e1 = g_caps_pk[(size_t)(2 * pg + 1) * NB + scolB];             \
      pb_h[t] = __byte_perm(e0, e1, 0x5410);                                  \
      pb_l[t] = __byte_perm(e0, e1, 0x7632);                                  \
    }                                                                         \
  }
#define STAGE(buf_)                                                           \
  {                                                                           \
    _Pragma("unroll") for (int t = 0; t < 2; t++) {                           \
      int p = skkA + 4 * t;                                                   \
      As_h[buf_][p * 72 + scolA] = pa_h[t];                                   \
      As_l[buf_][p * 72 + scolA] = pa_l[t];                                   \
    }                                                                         \
    _Pragma("unroll") for (int t = 0; t < 4; t++) {                           \
      int p = skkB + 2 * t;                                                   \
      Bs_h[buf_][p * 136 + scolB] = pb_h[t];                                  \
      Bs_l[buf_][p * 136 + scolB] = pb_l[t];                                  \
    }                                                                         \
  }
  PREFETCH(0);
  STAGE(0);
  __syncthreads();
  const int NCH = KR_SPLIT / 16;   // 22
  for (int kc = 0; kc < NCH; kc++) {
    if (kc + 1 < NCH) PREFETCH(kc + 1);
    const unsigned* Ah = As_h[kc & 1];
    const unsigned* Al = As_l[kc & 1];
    const unsigned* Bh = Bs_h[kc & 1];
    const unsigned* Bl = Bs_l[kc & 1];
    unsigned bh[4][2], bl[4][2];
#pragma unroll
    for (int nt = 0; nt < 4; nt++) {
      int col = pb + nt * 8 + gid;
      bh[nt][0] = Bh[tg * 136 + col];
      bh[nt][1] = Bh[(tg + 4) * 136 + col];
      bl[nt][0] = Bl[tg * 136 + col];
      bl[nt][1] = Bl[(tg + 4) * 136 + col];
    }
#pragma unroll
    for (int mt = 0; mt < 2; mt++) {
      int row = cb + mt * 16 + gid;
      unsigned ah[4] = {Ah[tg * 72 + row], Ah[tg * 72 + row + 8],
                        Ah[(tg + 4) * 72 + row], Ah[(tg + 4) * 72 + row + 8]};
      unsigned al[4] = {Al[tg * 72 + row], Al[tg * 72 + row + 8],
                        Al[(tg + 4) * 72 + row], Al[(tg + 4) * 72 + row + 8]};
#pragma unroll
      for (int nt = 0; nt < 4; nt++) {
        mma16(acc[mt][nt], ah, bh[nt]);
        mma16(acc[mt][nt], ah, bl[nt]);
        mma16(acc[mt][nt], al, bh[nt]);
      }
    }
    if (kc + 1 < NCH) STAGE((kc + 1) & 1);
    __syncthreads();
  }
  float* dst = g_spart + (size_t)split * NB * 256 + quarter * 64;
#pragma unroll
  for (int mt = 0; mt < 2; mt++) {
    int row = cb + mt * 16 + gid;     // oi local
#pragma unroll
    for (int nt = 0; nt < 4; nt++) {
      int col = pb + nt * 8 + 2 * tg; // b
      dst[(size_t)col * 256 + row] = acc[mt][nt][0] * 0.0625f;
      dst[(size_t)(col + 1) * 256 + row] = acc[mt][nt][1] * 0.0625f;
      dst[(size_t)col * 256 + row + 8] = acc[mt][nt][2] * 0.0625f;
      dst[(size_t)(col + 1) * 256 + row + 8] = acc[mt][nt][3] * 0.0625f;
    }
  }
#undef PREFETCH
#undef STAGE
}

// ---------------- routing pass 1/2 (scalar v2, proven) ----------------
__global__ void __launch_bounds__(256) k_route1() {
  __shared__ __align__(16) float ws[2 * 2048];
  __shared__ float red[256 * 9];       // logits, pitch 9 = conflict-free
  const int tid = threadIdx.x;
  const int bl = tid & 31;
  const int iq = (tid >> 5) & 3;
  const int oh = tid >> 7;
  const int b = blockIdx.y * 32 + bl;
  float outa[32];
#pragma unroll
  for (int o8 = 0; o8 < 8; o8++)
#pragma unroll
    for (int ii = 0; ii < 4; ii++)
      outa[o8 * 4 + ii] = g_out_sum[b * 256 + (oh * 8 + o8) * 16 + iq * 4 + ii];
  float s[32];
#pragma unroll
  for (int t = 0; t < 32; t++) s[t] = 0.f;
  const int n0 = blockIdx.x * NPC;
  float4 pre0, pre1;
  {
    const float4* sr = (const float4*)(g_wt + (size_t)n0 * 2048);
    pre0 = sr[tid]; pre1 = sr[tid + 256];
  }
  int cur = 0;
  for (int nn = 0; nn < NPC; nn++) {
    const int n = n0 + nn;
    float4* wbuf = (float4*)(ws + cur * 2048);
    wbuf[tid] = pre0; wbuf[tid + 256] = pre1;
    __syncthreads();
    if (nn + 1 < NPC) {
      const float4* sr = (const float4*)(g_wt + (size_t)(n + 1) * 2048);
      pre0 = sr[tid]; pre1 = sr[tid + 256];
    }
    float cj[8];
#pragma unroll
    for (int j = 0; j < 8; j++) cj[j] = g_caps[((size_t)n * 8 + j) * NB + b];
    const float* wb = ws + cur * 2048 + oh * 1024 + iq * 32;
    float v[32];
#pragma unroll
    for (int o8 = 0; o8 < 8; o8++) {
      const float4* w4 = (const float4*)(wb + o8 * 128);
#pragma unroll
      for (int ii = 0; ii < 4; ii++) {
        float4 a = w4[2 * ii], d = w4[2 * ii + 1];
        v[o8 * 4 + ii] = a.x * cj[0] + a.y * cj[1] + a.z * cj[2] + a.w * cj[3]
                       + d.x * cj[4] + d.y * cj[5] + d.z * cj[6] + d.w * cj[7];
      }
    }
#pragma unroll
    for (int o8 = 0; o8 < 8; o8++) {
      float lg = outa[o8 * 4] * v[o8 * 4] + outa[o8 * 4 + 1] * v[o8 * 4 + 1]
               + outa[o8 * 4 + 2] * v[o8 * 4 + 2] + outa[o8 * 4 + 3] * v[o8 * 4 + 3];
      red[tid * 9 + o8] = lg;
    }
    __syncthreads();
    float lg16[16];
    float m = -3.4e38f;
#pragma unroll
    for (int o = 0; o < 16; o++) {
      int hh = o >> 3, o8 = o & 7;
      float t = red[((hh * 4 + 0) * 32 + bl) * 9 + o8]
              + red[((hh * 4 + 1) * 32 + bl) * 9 + o8]
              + red[((hh * 4 + 2) * 32 + bl) * 9 + o8]
              + red[((hh * 4 + 3) * 32 + bl) * 9 + o8];
      lg16[o] = t;
      m = fmaxf(m, t);
    }
    float den = 0.f;
#pragma unroll
    for (int o = 0; o < 16; o++) { lg16[o] = __expf(lg16[o] - m); den += lg16[o]; }
    float inv = 1.f / den;
    float c[8];
#pragma unroll
    for (int o8 = 0; o8 < 8; o8++) c[o8] = lg16[oh * 8 + o8] * inv;
#pragma unroll
    for (int o8 = 0; o8 < 8; o8++)
#pragma unroll
      for (int ii = 0; ii < 4; ii++) s[o8 * 4 + ii] += c[o8] * v[o8 * 4 + ii];
    cur ^= 1;
  }
  float* dst = g_spart + ((size_t)blockIdx.x * NB + b) * 256;
#pragma unroll
  for (int o8 = 0; o8 < 8; o8++)
#pragma unroll
    for (int ii = 0; ii < 4; ii++)
      dst[(oh * 8 + o8) * 16 + iq * 4 + ii] = s[o8 * 4 + ii];
}

// ---------------- reduce partials + squash (+ final: length & mask) ----------------
__global__ void k_reduce_squash(const float* __restrict__ y, float* __restrict__ d_out,
                                int first, int final_) {
  const int b = blockIdx.x, tid = threadIdx.x;    // 256 threads = (o,i)
  float v = 0.f;
  for (int ch = 0; ch < NCHUNKS; ch++)
    v += g_spart[((size_t)ch * NB + b) * 256 + tid];
  float ss = v * v;
#pragma unroll
  for (int m = 1; m < 16; m <<= 1) ss += __shfl_xor_sync(0xffffffffu, ss, m);
  float nrm = sqrtf(ss);
  float sc = ss / (1.f + ss) / (nrm + 1e-8f);
  float ov = v * sc;
  if (!final_) {
    if (first) g_out_sum[b * 256 + tid] = ov;
    else g_out_sum[b * 256 + tid] += ov;
  } else {
    int o = tid >> 4, i = tid & 15;
    if (i == 0) d_out[b * NCLS + o] = sc * nrm;
    g_masked[b * 256 + tid] = ov * y[b * NCLS + o];
  }
}

// ---------------- decoder MLP ----------------
__global__ void k_dec1(const float* __restrict__ w1, const float* __restrict__ b1) {
  __shared__ float m[256];
  const int b = blockIdx.x, tid = threadIdx.x;    // 328 threads
  if (tid < 256) m[tid] = g_masked[b * 256 + tid];
  __syncthreads();
  float acc = b1[tid];
  for (int k = 0; k < 256; k++) acc += m[k] * w1[k * DEC1 + tid];
  g_r1[b * DEC1 + tid] = 1.f / (1.f + __expf(-acc));
}

__global__ void k_dec2(const float* __restrict__ w2, const float* __restrict__ b2) {
  __shared__ float m[DEC1];
  const int b = blockIdx.x, tid = threadIdx.x;    // 192 threads
  for (int i = tid; i < DEC1; i += DEC2) m[i] = g_r1[b * DEC1 + i];
  __syncthreads();
  float acc = b2[tid];
  for (int k = 0; k < DEC1; k++) acc += m[k] * w2[k * DEC2 + tid];
  g_r2[b * DEC2 + tid] = 1.f / (1.f + __expf(-acc));
}

// 8 batch rows per block: each w3 read reused 8x
__global__ void k_dec3(const float* __restrict__ w3, const float* __restrict__ b3,
                       float* __restrict__ d_out) {
  __shared__ float m[8 * DEC2];
  const int bq = blockIdx.y * 8;
  const int tid = threadIdx.x;
  const int j = blockIdx.x * 256 + tid;
  for (int i = tid; i < 8 * DEC2; i += 256)
    m[i] = g_r2[(bq + i / DEC2) * DEC2 + (i % DEC2)];
  __syncthreads();
  if (j >= DEC3) return;
  float acc[8];
  float bv = b3[j];
#pragma unroll
  for (int q = 0; q < 8; q++) acc[q] = bv;
  for (int k = 0; k < DEC2; k++) {
    float w = w3[(size_t)k * DEC3 + j];
#pragma unroll
    for (int q = 0; q < 8; q++) acc[q] += m[q * DEC2 + k] * w;
  }
#pragma unroll
  for (int q = 0; q < 8; q++)
    d_out[NB * NCLS + (size_t)(bq + q) * DEC3 + j] = acc[q];
}

// ---------------- launcher ----------------
extern "C" void kernel_launch(void* const* d_in, const int* in_sizes, int n_in,
                              void* d_out, int out_size) {
  const float* x   = (const float*)d_in[0];
  const float* y   = (const float*)d_in[1];
  const float* c1w = (const float*)d_in[2];
  const float* c1b = (const float*)d_in[3];
  const float* bng = (const float*)d_in[4];
  const float* bnb = (const float*)d_in[5];
  const float* c2w = (const float*)d_in[6];
  const float* c2b = (const float*)d_in[7];
  const float* cpw = (const float*)d_in[8];
  const float* dw1 = (const float*)d_in[9];
  const float* db1 = (const float*)d_in[10];
  const float* dw2 = (const float*)d_in[11];
  const float* db2 = (const float*)d_in[12];
  const float* dw3 = (const float*)d_in[13];
  const float* db3 = (const float*)d_in[14];
  float* out = (float*)d_out;
  (void)in_sizes; (void)n_in; (void)out_size;

  k_tr_both<<<dim3(81, 8), dim3(32, 8)>>>(c1w, c2w);
  k_conv1<<<dim3(8, NB), 256>>>(x, c1b);
  k_bnstats<<<C1, 256>>>(bng, bnb);
  k_conv2_mma<<<dim3(4, NB), 256>>>(c2b);   // launch #4 -> ncu capture slot
  k_squash<<<NCAPS, NB>>>();
  k_transpose_w<<<(NCLS * NCAPS * 128 + 255) / 256, 256>>>(cpw);

  k_route0_mma<<<dim3(4, NCHUNKS), 256>>>();
  k_reduce_squash<<<NB, 256>>>(y, out, 1, 0);
  k_route1<<<dim3(NCHUNKS, 4), 256>>>();
  k_reduce_squash<<<NB, 256>>>(y, out, 0, 0);
  k_route1<<<dim3(NCHUNKS, 4), 256>>>();
  k_reduce_squash<<<NB, 256>>>(y, out, 0, 1);

  k_dec1<<<NB, DEC1>>>(dw1, db1);
  k_dec2<<<NB, DEC2>>>(dw2, db2);
  k_dec3<<<dim3(27, 16), 256>>>(dw3, db3, out);
}

// round 16
// speedup vs baseline: 1.0832x; 1.0832x over previous
#include <cuda_runtime.h>
#include <cuda_bf16.h>
#include <math.h>

// ---------------- problem constants ----------------
namespace {
constexpr int NB = 128;                       // batch
constexpr int C0 = 30, H0 = 15, W0 = 15;      // input
constexpr int C1 = 256, W1 = 13, P1 = 169;    // after conv1 (13x13)
constexpr int C2 = 256, W2 = 11, P2 = 121;    // after conv2 (11x11)
constexpr int NCAPS = 3872, IND = 8, NCLS = 16;
constexpr int NFLAT = C2 * P2;                // 30976
constexpr int NCHUNKS = 88, NPC = 44;         // 88*44 = 3872
constexpr int DEC1 = 328, DEC2 = 192, DEC3 = 6750;
constexpr int K2 = 2304, KC = 16, NKC = K2 / KC;   // conv2 GEMM K
constexpr int K1P = 272, NKC1 = K1P / 16;          // conv1 GEMM K (270 padded)
constexpr int KR = NCAPS * IND;               // 30976 routing GEMM K
constexpr int KR_SPLIT = KR / NCHUNKS;        // 352 k per split
constexpr int XSZ = C0 * H0 * W0;             // 6750
}

// ---------------- scratch (static device memory, no allocs) ----------------
__device__ __align__(16) float g_h[NB * C1 * P1];            // conv1 out
__device__ __align__(16) float g_pbuf[NB * NFLAT];           // conv2 out
__device__ __align__(16) float g_caps[KR * NB];              // caps_t[n*8+j][b] fp32
__device__ __align__(16) unsigned g_caps_pk[KR * NB];        // caps bf16 (hi|lo<<16)
__device__ __align__(16) float g_wt[NCAPS * 2048];           // caps_w [n][o][i][j]
__device__ __align__(16) unsigned short g_wrph[(size_t)KR * 256];  // route w bf16 hi
__device__ __align__(16) unsigned short g_wrpl[(size_t)KR * 256];  // route w bf16 lo
__device__ __align__(16) unsigned short g_w1ph[K1P * 256];   // conv1 w bf16 hi, k-paired
__device__ __align__(16) unsigned short g_w1pl[K1P * 256];   // conv1 w bf16 lo, k-paired
__device__ __align__(16) unsigned short g_w2ph[K2 * 256];    // conv2 w bf16 hi, k-paired
__device__ __align__(16) unsigned short g_w2pl[K2 * 256];    // conv2 w bf16 lo, k-paired
__device__ __align__(16) unsigned g_xpk[NB * XSZ];           // x packed (hi|lo<<16)
__device__ __align__(16) unsigned g_hpk[NB * C1 * P1];       // relu(bn(h)) packed
__device__ __align__(16) float g_spart[(size_t)NCHUNKS * NB * 256];
__device__ __align__(16) float g_out_sum[NB * 256];
__device__ float g_masked[NB * 256];
__device__ float g_r1[NB * DEC1];
__device__ float g_r2[NB * DEC2];

__device__ __forceinline__ unsigned packf(float v) {
  __nv_bfloat16 bh = __float2bfloat16(v);
  float vh = __bfloat162float(bh);
  __nv_bfloat16 bl = __float2bfloat16(v - vh);
  return (unsigned)__bfloat16_as_ushort(bh) |
         ((unsigned)__bfloat16_as_ushort(bl) << 16);
}

// ---------------- pack input x to bf16 hi/lo ----------------
__global__ void k_packx(const float* __restrict__ x) {
  int i = blockIdx.x * 256 + threadIdx.x;
  if (i < NB * XSZ) g_xpk[i] = packf(x[i]);
}

// ---------------- fused transpose of both conv weights (to bf16 planes) ----------------
__global__ void k_tr_both(const float* __restrict__ c1w, const float* __restrict__ c2w) {
  const int c1 = blockIdx.x < 9;
  const float* __restrict__ src = c1 ? c1w : c2w;
  const int M = 256;
  const int N = c1 ? 270 : 2304;
  const int bx = c1 ? blockIdx.x : blockIdx.x - 9;
  __shared__ float t[32][33];
  const int tx = threadIdx.x;
  const int x = bx * 32 + tx;
  const int y0 = blockIdx.y * 32;
  for (int j = threadIdx.y; j < 32; j += 8) {
    int y = y0 + j;
    if (x < N && y < M) t[j][tx] = src[(size_t)y * N + x];
  }
  __syncthreads();
  const int xo = y0 + tx;   // co (M dim)
  const int yo0 = bx * 32;
  for (int j = threadIdx.y; j < 32; j += 8) {
    int yo = yo0 + j;       // k (N dim)
    if (xo < M) {
      if (c1) {
        if (yo < K1P) {
          float v = (yo < 270) ? t[tx][j] : 0.f;
          __nv_bfloat16 bh = __float2bfloat16(v);
          float vh = __bfloat162float(bh);
          __nv_bfloat16 bl = __float2bfloat16(v - vh);
          size_t idx = (size_t)(yo >> 1) * 512 + 2 * xo + (yo & 1);
          g_w1ph[idx] = __bfloat16_as_ushort(bh);
          g_w1pl[idx] = __bfloat16_as_ushort(bl);
        }
      } else if (yo < N) {
        float v = t[tx][j];
        __nv_bfloat16 bh = __float2bfloat16(v);
        float vh = __bfloat162float(bh);
        __nv_bfloat16 bl = __float2bfloat16(v - vh);
        size_t idx = (size_t)(yo >> 1) * 512 + 2 * xo + (yo & 1);
        g_w2ph[idx] = __bfloat16_as_ushort(bh);
        g_w2pl[idx] = __bfloat16_as_ushort(bl);
      }
    }
  }
}

// ---------------- caps_w transpose + route-GEMM weight planes ----------------
__global__ void k_transpose_w(const float* __restrict__ cw) {
  int idx = blockIdx.x * 256 + threadIdx.x;       // over 16*3872*128
  if (idx >= NCLS * NCAPS * 128) return;
  int o = idx / (NCAPS * 128);
  int rem = idx - o * (NCAPS * 128);
  int n = rem >> 7;
  int ij = rem & 127;
  float v = cw[idx];
  g_wt[n * 2048 + o * 128 + ij] = v;
  int i = ij >> 3, j = ij & 7;
  int nj = n * 8 + j, oi = o * 16 + i;
  __nv_bfloat16 bh = __float2bfloat16(v);
  float vh = __bfloat162float(bh);
  __nv_bfloat16 bl = __float2bfloat16(v - vh);
  size_t widx = (size_t)(nj >> 1) * 512 + 2 * oi + (nj & 1);
  g_wrph[widx] = __bfloat16_as_ushort(bh);
  g_wrpl[widx] = __bfloat16_as_ushort(bl);
}

// ---------------- shared MMA helper ----------------
__device__ __forceinline__ void mma16(float* c, const unsigned* a, const unsigned* b) {
  asm volatile(
      "mma.sync.aligned.m16n8k16.row.col.f32.bf16.bf16.f32 "
      "{%0,%1,%2,%3},{%4,%5,%6,%7},{%8,%9},{%0,%1,%2,%3};"
      : "+f"(c[0]), "+f"(c[1]), "+f"(c[2]), "+f"(c[3])
      : "r"(a[0]), "r"(a[1]), "r"(a[2]), "r"(a[3]), "r"(b[0]), "r"(b[1]));
}

// ---------------- conv1 as implicit GEMM (3-term bf16 k16) ----------------
// grid (2 co-halves, 2 pos-tiles, NB); block = 8 warps (2M x 4N), M=128 co, N=128 pos
__global__ void __launch_bounds__(256, 2) k_conv1_mma(const float* __restrict__ b1c) {
  __shared__ __align__(16) unsigned As_h[2][8 * 136];
  __shared__ __align__(16) unsigned As_l[2][8 * 136];
  __shared__ __align__(16) unsigned Bs_h[2][8 * 136];
  __shared__ __align__(16) unsigned Bs_l[2][8 * 136];
  __shared__ int offs_s[K1P];
  __shared__ int posoff_s[128];
  const int cbt = blockIdx.x, pt = blockIdx.y, b = blockIdx.z;
  const int tid = threadIdx.x;
  for (int i = tid; i < K1P; i += 256) {
    if (i < 270) {
      int ci = i / 9, r = i - 9 * ci;
      int kh = r / 3, kw = r - 3 * kh;
      offs_s[i] = ci * (H0 * W0) + kh * W0 + kw;
    } else {
      offs_s[i] = 0;
    }
  }
  if (tid < 128) {
    int p = pt * 128 + tid;
    posoff_s[tid] = (p < P1) ? (p / W1) * W0 + (p - (p / W1) * W1) : 0;
  }
  const int lane = tid & 31, gid = lane >> 2, tg = lane & 3;
  const int w = tid >> 5, wm = w >> 2, wn = w & 3;
  const int cb = wm * 64, pb = wn * 32;
  float acc[4][4][4];
#pragma unroll
  for (int mt = 0; mt < 4; mt++)
#pragma unroll
    for (int nt = 0; nt < 4; nt++)
#pragma unroll
      for (int q = 0; q < 4; q++) acc[mt][nt][q] = 0.f;
  const unsigned* __restrict__ xpk = g_xpk + (size_t)b * XSZ;
  const unsigned* __restrict__ wAh = (const unsigned*)g_w1ph;
  const unsigned* __restrict__ wAl = (const unsigned*)g_w1pl;
  const int skk0 = tid >> 7, scol = tid & 127;
  const int coA = cbt * 128 + scol;
  const bool pvalid = (pt * 128 + scol) < P1;
  unsigned pa_h[4], pa_l[4], pb_h[4], pb_l[4];
#define PREFETCH(kc_)                                                         \
  {                                                                           \
    _Pragma("unroll") for (int t = 0; t < 4; t++) {                           \
      int p = skk0 + 2 * t;                                                   \
      int k2g = (kc_) * 8 + p;                                                \
      pa_h[t] = wAh[(size_t)k2g * 256 + coA];                                 \
      pa_l[t] = wAl[(size_t)k2g * 256 + coA];                                 \
      unsigned e0 = 0, e1 = 0;                                                \
      if (pvalid) {                                                           \
        int po = posoff_s[scol];                                              \
        int kg = (kc_) * 16 + 2 * p;                                          \
        e0 = xpk[offs_s[kg] + po];                                            \
        e1 = xpk[offs_s[kg + 1] + po];                                        \
      }                                                                       \
      pb_h[t] = __byte_perm(e0, e1, 0x5410);                                  \
      pb_l[t] = __byte_perm(e0, e1, 0x7632);                                  \
    }                                                                         \
  }
#define STAGE(buf_)                                                           \
  {                                                                           \
    _Pragma("unroll") for (int t = 0; t < 4; t++) {                           \
      int p = skk0 + 2 * t;                                                   \
      As_h[buf_][p * 136 + scol] = pa_h[t];                                   \
      As_l[buf_][p * 136 + scol] = pa_l[t];                                   \
      Bs_h[buf_][p * 136 + scol] = pb_h[t];                                   \
      Bs_l[buf_][p * 136 + scol] = pb_l[t];                                   \
    }                                                                         \
  }
  __syncthreads();
  PREFETCH(0);
  STAGE(0);
  __syncthreads();
  for (int kc = 0; kc < NKC1; kc++) {
    if (kc + 1 < NKC1) PREFETCH(kc + 1);
    const unsigned* Ah = As_h[kc & 1];
    const unsigned* Al = As_l[kc & 1];
    const unsigned* Bh = Bs_h[kc & 1];
    const unsigned* Bl = Bs_l[kc & 1];
    unsigned bh[4][2], bl[4][2];
#pragma unroll
    for (int nt = 0; nt < 4; nt++) {
      int col = pb + nt * 8 + gid;
      bh[nt][0] = Bh[tg * 136 + col];
      bh[nt][1] = Bh[(tg + 4) * 136 + col];
      bl[nt][0] = Bl[tg * 136 + col];
      bl[nt][1] = Bl[(tg + 4) * 136 + col];
    }
#pragma unroll
    for (int mt = 0; mt < 4; mt++) {
      int row = cb + mt * 16 + gid;
      unsigned ah[4] = {Ah[tg * 136 + row], Ah[tg * 136 + row + 8],
                        Ah[(tg + 4) * 136 + row], Ah[(tg + 4) * 136 + row + 8]};
      unsigned al[4] = {Al[tg * 136 + row], Al[tg * 136 + row + 8],
                        Al[(tg + 4) * 136 + row], Al[(tg + 4) * 136 + row + 8]};
#pragma unroll
      for (int nt = 0; nt < 4; nt++) {
        mma16(acc[mt][nt], ah, bh[nt]);
        mma16(acc[mt][nt], ah, bl[nt]);
        mma16(acc[mt][nt], al, bh[nt]);
      }
    }
    if (kc + 1 < NKC1) STAGE((kc + 1) & 1);
    __syncthreads();
  }
#pragma unroll
  for (int mt = 0; mt < 4; mt++) {
    int co = cbt * 128 + cb + mt * 16 + gid;
    float bs0 = b1c[co], bs1 = b1c[co + 8];
#pragma unroll
    for (int nt = 0; nt < 4; nt++) {
      int pl = pb + nt * 8 + 2 * tg;
      int pg = pt * 128 + pl;
      if (pg < P1) {
        g_h[((size_t)b * C1 + co) * P1 + pg] = acc[mt][nt][0] + bs0;
        g_h[((size_t)b * C1 + co + 8) * P1 + pg] = acc[mt][nt][2] + bs1;
      }
      if (pg + 1 < P1 && pl + 1 < 128) {
        g_h[((size_t)b * C1 + co) * P1 + pg + 1] = acc[mt][nt][1] + bs0;
        g_h[((size_t)b * C1 + co + 8) * P1 + pg + 1] = acc[mt][nt][3] + bs1;
      }
    }
  }
#undef PREFETCH
#undef STAGE
}

// ---------------- batchnorm stats + fused BN+relu+bf16-split pack ----------------
__global__ void k_bnstats(const float* __restrict__ gamma, const float* __restrict__ beta) {
  const int c = blockIdx.x, tid = threadIdx.x;
  float s = 0.f, s2 = 0.f;
  for (int i = tid; i < NB * P1; i += 256) {
    int b = i / P1, p = i - (i / P1) * P1;
    float v = g_h[((size_t)b * C1 + c) * P1 + p];
    s += v; s2 += v * v;
  }
  __shared__ float rs[256], rq[256];
  __shared__ float ssc, ssh;
  rs[tid] = s; rq[tid] = s2;
  __syncthreads();
  for (int st = 128; st > 0; st >>= 1) {
    if (tid < st) { rs[tid] += rs[tid + st]; rq[tid] += rq[tid + st]; }
    __syncthreads();
  }
  if (tid == 0) {
    const float inv_n = 1.f / (float)(NB * P1);
    float mean = rs[0] * inv_n;
    float var = fmaxf(rq[0] * inv_n - mean * mean, 0.f);
    float sc = gamma[c] * rsqrtf(var + 1e-5f);
    ssc = sc;
    ssh = beta[c] - mean * sc;
  }
  __syncthreads();
  const float sc = ssc, sh = ssh;
  for (int i = tid; i < NB * P1; i += 256) {
    int b = i / P1, p = i - (i / P1) * P1;
    size_t idx = ((size_t)b * C1 + c) * P1 + p;
    float v = g_h[idx] * sc + sh;
    v = v > 0.f ? v : 0.f;
    g_hpk[idx] = packf(v);
  }
}

// ---------------- conv2 as implicit GEMM (R14 proven config) ----------------
__global__ void __launch_bounds__(256, 2) k_conv2_mma(const float* __restrict__ b2) {
  __shared__ __align__(16) unsigned As_h[2][8 * 136];
  __shared__ __align__(16) unsigned As_l[2][8 * 136];
  __shared__ __align__(16) unsigned Bs_h[2][8 * 136];
  __shared__ __align__(16) unsigned Bs_l[2][8 * 136];
  __shared__ int offs_s[K2];
  __shared__ int posoff_s[128];
  const int b = blockIdx.y, cbt = blockIdx.x;
  const int tid = threadIdx.x;
  for (int i = tid; i < K2; i += 256) {
    int ci = i / 9, r = i - 9 * ci;
    int kh = r / 3, kw = r - 3 * kh;
    offs_s[i] = ci * P1 + kh * W1 + kw;
  }
  if (tid < 128) posoff_s[tid] = (tid / 11) * W1 + (tid - (tid / 11) * 11);
  const int lane = tid & 31, gid = lane >> 2, tg = lane & 3;
  const int w = tid >> 5, wm = w >> 2, wn = w & 3;
  const int cb = wm * 64, pb = wn * 32;
  float acc[4][4][4];
#pragma unroll
  for (int mt = 0; mt < 4; mt++)
#pragma unroll
    for (int nt = 0; nt < 4; nt++)
#pragma unroll
      for (int q = 0; q < 4; q++) acc[mt][nt][q] = 0.f;
  const unsigned* __restrict__ hpk = g_hpk + (size_t)b * C1 * P1;
  const unsigned* __restrict__ wAh = (const unsigned*)g_w2ph;
  const unsigned* __restrict__ wAl = (const unsigned*)g_w2pl;
  const int skk0 = tid >> 7, scol = tid & 127;
  const int coA = cbt * 128 + scol;
  unsigned pa_h[4], pa_l[4], pb_h[4], pb_l[4];
#define PREFETCH(kc_)                                                         \
  {                                                                           \
    _Pragma("unroll") for (int t = 0; t < 4; t++) {                           \
      int p = skk0 + 2 * t;                                                   \
      int k2g = (kc_) * 8 + p;                                                \
      pa_h[t] = wAh[(size_t)k2g * 256 + coA];                                 \
      pa_l[t] = wAl[(size_t)k2g * 256 + coA];                                 \
      unsigned e0 = 0, e1 = 0;                                                \
      if (scol < 121) {                                                       \
        int po = posoff_s[scol];                                              \
        int kg = (kc_) * KC + 2 * p;                                          \
        e0 = hpk[offs_s[kg] + po];                                            \
        e1 = hpk[offs_s[kg + 1] + po];                                        \
      }                                                                       \
      pb_h[t] = __byte_perm(e0, e1, 0x5410);                                  \
      pb_l[t] = __byte_perm(e0, e1, 0x7632);                                  \
    }                                                                         \
  }
#define STAGE(buf_)                                                           \
  {                                                                           \
    _Pragma("unroll") for (int t = 0; t < 4; t++) {                           \
      int p = skk0 + 2 * t;                                                   \
      As_h[buf_][p * 136 + scol] = pa_h[t];                                   \
      As_l[buf_][p * 136 + scol] = pa_l[t];                                   \
      Bs_h[buf_][p * 136 + scol] = pb_h[t];                                   \
      Bs_l[buf_][p * 136 + scol] = pb_l[t];                                   \
    }                                                                         \
  }
  __syncthreads();
  PREFETCH(0);
  STAGE(0);
  __syncthreads();
  for (int kc = 0; kc < NKC; kc++) {
    if (kc + 1 < NKC) PREFETCH(kc + 1);
    const unsigned* Ah = As_h[kc & 1];
    const unsigned* Al = As_l[kc & 1];
    const unsigned* Bh = Bs_h[kc & 1];
    const unsigned* Bl = Bs_l[kc & 1];
    unsigned bh[4][2], bl[4][2];
#pragma unroll
    for (int nt = 0; nt < 4; nt++) {
      int col = pb + nt * 8 + gid;
      bh[nt][0] = Bh[tg * 136 + col];
      bh[nt][1] = Bh[(tg + 4) * 136 + col];
      bl[nt][0] = Bl[tg * 136 + col];
      bl[nt][1] = Bl[(tg + 4) * 136 + col];
    }
#pragma unroll
    for (int mt = 0; mt < 4; mt++) {
      int row = cb + mt * 16 + gid;
      unsigned ah[4] = {Ah[tg * 136 + row], Ah[tg * 136 + row + 8],
                        Ah[(tg + 4) * 136 + row], Ah[(tg + 4) * 136 + row + 8]};
      unsigned al[4] = {Al[tg * 136 + row], Al[tg * 136 + row + 8],
                        Al[(tg + 4) * 136 + row], Al[(tg + 4) * 136 + row + 8]};
#pragma unroll
      for (int nt = 0; nt < 4; nt++) {
        mma16(acc[mt][nt], ah, bh[nt]);
        mma16(acc[mt][nt], ah, bl[nt]);
        mma16(acc[mt][nt], al, bh[nt]);
      }
    }
    if (kc + 1 < NKC) STAGE((kc + 1) & 1);
    __syncthreads();
  }
  float* outb = g_pbuf + (size_t)b * NFLAT;
#pragma unroll
  for (int mt = 0; mt < 4; mt++) {
    int co = cbt * 128 + cb + mt * 16 + gid;
    float bs0 = b2[co], bs1 = b2[co + 8];
#pragma unroll
    for (int nt = 0; nt < 4; nt++) {
      int p = pb + nt * 8 + 2 * tg;
      if (p < P2) {
        outb[co * P2 + p] = acc[mt][nt][0] + bs0;
        outb[(co + 8) * P2 + p] = acc[mt][nt][2] + bs1;
      }
      if (p + 1 < P2) {
        outb[co * P2 + p + 1] = acc[mt][nt][1] + bs0;
        outb[(co + 8) * P2 + p + 1] = acc[mt][nt][3] + bs1;
      }
    }
  }
#undef PREFETCH
#undef STAGE
}

// ---------------- primary capsule squash + transpose + bf16 pack ----------------
__global__ void k_squash(void) {
  const int n = blockIdx.x, b = threadIdx.x;
  const float4* src = (const float4*)(g_pbuf + (size_t)b * NFLAT + n * IND);
  float4 a0 = src[0], a1 = src[1];
  float v[8] = {a0.x, a0.y, a0.z, a0.w, a1.x, a1.y, a1.z, a1.w};
  float ss = 0.f;
#pragma unroll
  for (int j = 0; j < 8; j++) ss += v[j] * v[j];
  float nrm = sqrtf(ss);
  float sc = ss / (1.f + ss) / (nrm + 1e-8f);
#pragma unroll
  for (int j = 0; j < 8; j++) {
    float cv = v[j] * sc;
    size_t idx = ((size_t)n * IND + j) * NB + b;
    g_caps[idx] = cv;
    g_caps_pk[idx] = packf(cv);
  }
}

// ---------------- routing pass0 as GEMM (R14 proven config) ----------------
__global__ void __launch_bounds__(256, 2) k_route0_mma() {
  __shared__ __align__(16) unsigned As_h[2][8 * 136];
  __shared__ __align__(16) unsigned As_l[2][8 * 136];
  __shared__ __align__(16) unsigned Bs_h[2][8 * 136];
  __shared__ __align__(16) unsigned Bs_l[2][8 * 136];
  const int half = blockIdx.x, split = blockIdx.y;
  const int tid = threadIdx.x;
  const int lane = tid & 31, gid = lane >> 2, tg = lane & 3;
  const int w = tid >> 5, wm = w >> 2, wn = w & 3;
  const int cb = wm * 64, pb = wn * 32;
  float acc[4][4][4];
#pragma unroll
  for (int mt = 0; mt < 4; mt++)
#pragma unroll
    for (int nt = 0; nt < 4; nt++)
#pragma unroll
      for (int q = 0; q < 4; q++) acc[mt][nt][q] = 0.f;
  const unsigned* __restrict__ wAh = (const unsigned*)g_wrph;
  const unsigned* __restrict__ wAl = (const unsigned*)g_wrpl;
  const int skk0 = tid >> 7, scol = tid & 127;
  const int oiA = half * 128 + scol;
  const int kp0 = split * (KR_SPLIT / 2);
  unsigned pa_h[4], pa_l[4], pb_h[4], pb_l[4];
#define PREFETCH(kc_)                                                         \
  {                                                                           \
    _Pragma("unroll") for (int t = 0; t < 4; t++) {                           \
      int p = skk0 + 2 * t;                                                   \
      int pg = kp0 + (kc_) * 8 + p;                                           \
      pa_h[t] = wAh[(size_t)pg * 256 + oiA];                                  \
      pa_l[t] = wAl[(size_t)pg * 256 + oiA];                                  \
      unsigned e0 = g_caps_pk[(size_t)(2 * pg) * NB + scol];                  \
      unsigned e1 = g_caps_pk[(size_t)(2 * pg + 1) * NB + scol];              \
      pb_h[t] = __byte_perm(e0, e1, 0x5410);                                  \
      pb_l[t] = __byte_perm(e0, e1, 0x7632);                                  \
    }                                                                         \
  }
#define STAGE(buf_)                                                           \
  {                                                                           \
    _Pragma("unroll") for (int t = 0; t < 4; t++) {                           \
      int p = skk0 + 2 * t;                                                   \
      As_h[buf_][p * 136 + scol] = pa_h[t];                                   \
      As_l[buf_][p * 136 + scol] = pa_l[t];                                   \
      Bs_h[buf_][p * 136 + scol] = pb_h[t];                                   \
      Bs_l[buf_][p * 136 + scol] = pb_l[t];                                   \
    }                                                                         \
  }
  PREFETCH(0);
  STAGE(0);
  __syncthreads();
  const int NCH = KR_SPLIT / 16;   // 22
  for (int kc = 0; kc < NCH; kc++) {
    if (kc + 1 < NCH) PREFETCH(kc + 1);
    const unsigned* Ah = As_h[kc & 1];
    const unsigned* Al = As_l[kc & 1];
    const unsigned* Bh = Bs_h[kc & 1];
    const unsigned* Bl = Bs_l[kc & 1];
    unsigned bh[4][2], bl[4][2];
#pragma unroll
    for (int nt = 0; nt < 4; nt++) {
      int col = pb + nt * 8 + gid;
      bh[nt][0] = Bh[tg * 136 + col];
      bh[nt][1] = Bh[(tg + 4) * 136 + col];
      bl[nt][0] = Bl[tg * 136 + col];
      bl[nt][1] = Bl[(tg + 4) * 136 + col];
    }
#pragma unroll
    for (int mt = 0; mt < 4; mt++) {
      int row = cb + mt * 16 + gid;
      unsigned ah[4] = {Ah[tg * 136 + row], Ah[tg * 136 + row + 8],
                        Ah[(tg + 4) * 136 + row], Ah[(tg + 4) * 136 + row + 8]};
      unsigned al[4] = {Al[tg * 136 + row], Al[tg * 136 + row + 8],
                        Al[(tg + 4) * 136 + row], Al[(tg + 4) * 136 + row + 8]};
#pragma unroll
      for (int nt = 0; nt < 4; nt++) {
        mma16(acc[mt][nt], ah, bh[nt]);
        mma16(acc[mt][nt], ah, bl[nt]);
        mma16(acc[mt][nt], al, bh[nt]);
      }
    }
    if (kc + 1 < NCH) STAGE((kc + 1) & 1);
    __syncthreads();
  }
  float* dst = g_spart + (size_t)split * NB * 256 + half * 128;
#pragma unroll
  for (int mt = 0; mt < 4; mt++) {
    int row = cb + mt * 16 + gid;     // oi local
#pragma unroll
    for (int nt = 0; nt < 4; nt++) {
      int col = pb + nt * 8 + 2 * tg; // b
      dst[(size_t)col * 256 + row] = acc[mt][nt][0] * 0.0625f;
      dst[(size_t)(col + 1) * 256 + row] = acc[mt][nt][1] * 0.0625f;
      dst[(size_t)col * 256 + row + 8] = acc[mt][nt][2] * 0.0625f;
      dst[(size_t)(col + 1) * 256 + row + 8] = acc[mt][nt][3] * 0.0625f;
    }
  }
#undef PREFETCH
#undef STAGE
}

// ---------------- routing pass 1/2 (scalar v2, proven) ----------------
__global__ void __launch_bounds__(256) k_route1() {
  __shared__ __align__(16) float ws[2 * 2048];
  __shared__ float red[256 * 9];
  const int tid = threadIdx.x;
  const int bl = tid & 31;
  const int iq = (tid >> 5) & 3;
  const int oh = tid >> 7;
  const int b = blockIdx.y * 32 + bl;
  float outa[32];
#pragma unroll
  for (int o8 = 0; o8 < 8; o8++)
#pragma unroll
    for (int ii = 0; ii < 4; ii++)
      outa[o8 * 4 + ii] = g_out_sum[b * 256 + (oh * 8 + o8) * 16 + iq * 4 + ii];
  float s[32];
#pragma unroll
  for (int t = 0; t < 32; t++) s[t] = 0.f;
  const int n0 = blockIdx.x * NPC;
  float4 pre0, pre1;
  {
    const float4* sr = (const float4*)(g_wt + (size_t)n0 * 2048);
    pre0 = sr[tid]; pre1 = sr[tid + 256];
  }
  int cur = 0;
  for (int nn = 0; nn < NPC; nn++) {
    const int n = n0 + nn;
    float4* wbuf = (float4*)(ws + cur * 2048);
    wbuf[tid] = pre0; wbuf[tid + 256] = pre1;
    __syncthreads();
    if (nn + 1 < NPC) {
      const float4* sr = (const float4*)(g_wt + (size_t)(n + 1) * 2048);
      pre0 = sr[tid]; pre1 = sr[tid + 256];
    }
    float cj[8];
#pragma unroll
    for (int j = 0; j < 8; j++) cj[j] = g_caps[((size_t)n * 8 + j) * NB + b];
    const float* wb = ws + cur * 2048 + oh * 1024 + iq * 32;
    float v[32];
#pragma unroll
    for (int o8 = 0; o8 < 8; o8++) {
      const float4* w4 = (const float4*)(wb + o8 * 128);
#pragma unroll
      for (int ii = 0; ii < 4; ii++) {
        float4 a = w4[2 * ii], d = w4[2 * ii + 1];
        v[o8 * 4 + ii] = a.x * cj[0] + a.y * cj[1] + a.z * cj[2] + a.w * cj[3]
                       + d.x * cj[4] + d.y * cj[5] + d.z * cj[6] + d.w * cj[7];
      }
    }
#pragma unroll
    for (int o8 = 0; o8 < 8; o8++) {
      float lg = outa[o8 * 4] * v[o8 * 4] + outa[o8 * 4 + 1] * v[o8 * 4 + 1]
               + outa[o8 * 4 + 2] * v[o8 * 4 + 2] + outa[o8 * 4 + 3] * v[o8 * 4 + 3];
      red[tid * 9 + o8] = lg;
    }
    __syncthreads();
    float lg16[16];
    float m = -3.4e38f;
#pragma unroll
    for (int o = 0; o < 16; o++) {
      int hh = o >> 3, o8 = o & 7;
      float t = red[((hh * 4 + 0) * 32 + bl) * 9 + o8]
              + red[((hh * 4 + 1) * 32 + bl) * 9 + o8]
              + red[((hh * 4 + 2) * 32 + bl) * 9 + o8]
              + red[((hh * 4 + 3) * 32 + bl) * 9 + o8];
      lg16[o] = t;
      m = fmaxf(m, t);
    }
    float den = 0.f;
#pragma unroll
    for (int o = 0; o < 16; o++) { lg16[o] = __expf(lg16[o] - m); den += lg16[o]; }
    float inv = 1.f / den;
    float c[8];
#pragma unroll
    for (int o8 = 0; o8 < 8; o8++) c[o8] = lg16[oh * 8 + o8] * inv;
#pragma unroll
    for (int o8 = 0; o8 < 8; o8++)
#pragma unroll
      for (int ii = 0; ii < 4; ii++) s[o8 * 4 + ii] += c[o8] * v[o8 * 4 + ii];
    cur ^= 1;
  }
  float* dst = g_spart + ((size_t)blockIdx.x * NB + b) * 256;
#pragma unroll
  for (int o8 = 0; o8 < 8; o8++)
#pragma unroll
    for (int ii = 0; ii < 4; ii++)
      dst[(oh * 8 + o8) * 16 + iq * 4 + ii] = s[o8 * 4 + ii];
}

// ---------------- reduce partials + squash (+ final: length & mask) ----------------
__global__ void k_reduce_squash(const float* __restrict__ y, float* __restrict__ d_out,
                                int first, int final_) {
  const int b = blockIdx.x, tid = threadIdx.x;
  float v = 0.f;
  for (int ch = 0; ch < NCHUNKS; ch++)
    v += g_spart[((size_t)ch * NB + b) * 256 + tid];
  float ss = v * v;
#pragma unroll
  for (int m = 1; m < 16; m <<= 1) ss += __shfl_xor_sync(0xffffffffu, ss, m);
  float nrm = sqrtf(ss);
  float sc = ss / (1.f + ss) / (nrm + 1e-8f);
  float ov = v * sc;
  if (!final_) {
    if (first) g_out_sum[b * 256 + tid] = ov;
    else g_out_sum[b * 256 + tid] += ov;
  } else {
    int o = tid >> 4, i = tid & 15;
    if (i == 0) d_out[b * NCLS + o] = sc * nrm;
    g_masked[b * 256 + tid] = ov * y[b * NCLS + o];
  }
}

// ---------------- decoder MLP ----------------
__global__ void k_dec1(const float* __restrict__ w1, const float* __restrict__ b1) {
  __shared__ float m[256];
  const int b = blockIdx.x, tid = threadIdx.x;
  if (tid < 256) m[tid] = g_masked[b * 256 + tid];
  __syncthreads();
  float acc = b1[tid];
  for (int k = 0; k < 256; k++) acc += m[k] * w1[k * DEC1 + tid];
  g_r1[b * DEC1 + tid] = 1.f / (1.f + __expf(-acc));
}

__global__ void k_dec2(const float* __restrict__ w2, const float* __restrict__ b2) {
  __shared__ float m[DEC1];
  const int b = blockIdx.x, tid = threadIdx.x;
  for (int i = tid; i < DEC1; i += DEC2) m[i] = g_r1[b * DEC1 + i];
  __syncthreads();
  float acc = b2[tid];
  for (int k = 0; k < DEC1; k++) acc += m[k] * w2[k * DEC2 + tid];
  g_r2[b * DEC2 + tid] = 1.f / (1.f + __expf(-acc));
}

__global__ void k_dec3(const float* __restrict__ w3, const float* __restrict__ b3,
                       float* __restrict__ d_out) {
  __shared__ float m[8 * DEC2];
  const int bq = blockIdx.y * 8;
  const int tid = threadIdx.x;
  const int j = blockIdx.x * 256 + tid;
  for (int i = tid; i < 8 * DEC2; i += 256)
    m[i] = g_r2[(bq + i / DEC2) * DEC2 + (i % DEC2)];
  __syncthreads();
  if (j >= DEC3) return;
  float acc[8];
  float bv = b3[j];
#pragma unroll
  for (int q = 0; q < 8; q++) acc[q] = bv;
  for (int k = 0; k < DEC2; k++) {
    float w = w3[(size_t)k * DEC3 + j];
#pragma unroll
    for (int q = 0; q < 8; q++) acc[q] += m[q * DEC2 + k] * w;
  }
#pragma unroll
  for (int q = 0; q < 8; q++)
    d_out[NB * NCLS + (size_t)(bq + q) * DEC3 + j] = acc[q];
}

// ---------------- launcher ----------------
extern "C" void kernel_launch(void* const* d_in, const int* in_sizes, int n_in,
                              void* d_out, int out_size) {
  const float* x   = (const float*)d_in[0];
  const float* y   = (const float*)d_in[1];
  const float* c1w = (const float*)d_in[2];
  const float* c1b = (const float*)d_in[3];
  const float* bng = (const float*)d_in[4];
  const float* bnb = (const float*)d_in[5];
  const float* c2w = (const float*)d_in[6];
  const float* c2b = (const float*)d_in[7];
  const float* cpw = (const float*)d_in[8];
  const float* dw1 = (const float*)d_in[9];
  const float* db1 = (const float*)d_in[10];
  const float* dw2 = (const float*)d_in[11];
  const float* db2 = (const float*)d_in[12];
  const float* dw3 = (const float*)d_in[13];
  const float* db3 = (const float*)d_in[14];
  float* out = (float*)d_out;
  (void)in_sizes; (void)n_in; (void)out_size;

  k_packx<<<(NB * XSZ + 255) / 256, 256>>>(x);
  k_tr_both<<<dim3(81, 8), dim3(32, 8)>>>(c1w, c2w);
  k_transpose_w<<<(NCLS * NCAPS * 128 + 255) / 256, 256>>>(cpw);
  k_conv1_mma<<<dim3(2, 2, NB), 256>>>(c1b);   // launch #4 -> ncu capture slot
  k_bnstats<<<C1, 256>>>(bng, bnb);
  k_conv2_mma<<<dim3(2, NB), 256>>>(c2b);
  k_squash<<<NCAPS, NB>>>();

  k_route0_mma<<<dim3(2, NCHUNKS), 256>>>();
  k_reduce_squash<<<NB, 256>>>(y, out, 1, 0);
  k_route1<<<dim3(NCHUNKS, 4), 256>>>();
  k_reduce_squash<<<NB, 256>>>(y, out, 0, 0);
  k_route1<<<dim3(NCHUNKS, 4), 256>>>();
  k_reduce_squash<<<NB, 256>>>(y, out, 0, 1);

  k_dec1<<<NB, DEC1>>>(dw1, db1);
  k_dec2<<<NB, DEC2>>>(dw2, db2);
  k_dec3<<<dim3(27, 16), 256>>>(dw3, db3, out);
}

// round 17
// speedup vs baseline: 1.0891x; 1.0055x over previous
#include <cuda_runtime.h>
#include <cuda_bf16.h>
#include <math.h>

// ---------------- problem constants ----------------
namespace {
constexpr int NB = 128;                       // batch
constexpr int C0 = 30, H0 = 15, W0 = 15;      // input
constexpr int C1 = 256, W1 = 13, P1 = 169;    // after conv1 (13x13)
constexpr int C2 = 256, W2 = 11, P2 = 121;    // after conv2 (11x11)
constexpr int NCAPS = 3872, IND = 8, NCLS = 16;
constexpr int NFLAT = C2 * P2;                // 30976
constexpr int NCHUNKS = 88, NPC = 44;         // 88*44 = 3872
constexpr int DEC1 = 328, DEC2 = 192, DEC3 = 6750;
constexpr int K2 = 2304, KC = 16, NKC = K2 / KC;   // conv2 GEMM K
constexpr int K1P = 272, NKC1 = K1P / 16;          // conv1 GEMM K (270 padded)
constexpr int KR = NCAPS * IND;               // 30976 routing GEMM K
constexpr int KR_SPLIT = KR / NCHUNKS;        // 352 k per split
constexpr int XSZ = C0 * H0 * W0;             // 6750
}

// ---------------- scratch (static device memory, no allocs) ----------------
__device__ __align__(16) float g_h[NB * C1 * P1];            // conv1 out
__device__ __align__(16) float g_pbuf[NB * NFLAT];           // conv2 out
__device__ __align__(16) float g_caps[KR * NB];              // caps_t[n*8+j][b] fp32
__device__ __align__(16) unsigned g_caps_pk[KR * NB];        // caps bf16 (hi|lo<<16)
__device__ __align__(16) float g_wt[NCAPS * 2048];           // caps_w [n][o][i][j]
__device__ __align__(16) unsigned short g_wrph[(size_t)KR * 256];  // route w bf16 hi
__device__ __align__(16) unsigned short g_wrpl[(size_t)KR * 256];  // route w bf16 lo
__device__ __align__(16) unsigned short g_w1ph[K1P * 256];   // conv1 w bf16 hi, k-paired
__device__ __align__(16) unsigned short g_w1pl[K1P * 256];   // conv1 w bf16 lo, k-paired
__device__ __align__(16) unsigned short g_w2ph[K2 * 256];    // conv2 w bf16 hi, k-paired
__device__ __align__(16) unsigned short g_w2pl[K2 * 256];    // conv2 w bf16 lo, k-paired
__device__ __align__(16) unsigned g_xpk[NB * XSZ];           // x packed (hi|lo<<16)
__device__ __align__(16) unsigned g_hpk[NB * C1 * P1];       // relu(bn(h)) packed
__device__ __align__(16) float g_spart[(size_t)NCHUNKS * NB * 256];
__device__ __align__(16) float g_out_sum[NB * 256];
__device__ float g_masked[NB * 256];
__device__ float g_r2[NB * DEC2];

__device__ __forceinline__ unsigned packf(float v) {
  __nv_bfloat16 bh = __float2bfloat16(v);
  float vh = __bfloat162float(bh);
  __nv_bfloat16 bl = __float2bfloat16(v - vh);
  return (unsigned)__bfloat16_as_ushort(bh) |
         ((unsigned)__bfloat16_as_ushort(bl) << 16);
}

// ---------------- pack input x to bf16 hi/lo ----------------
__global__ void k_packx(const float* __restrict__ x) {
  int i = blockIdx.x * 256 + threadIdx.x;
  if (i < NB * XSZ) g_xpk[i] = packf(x[i]);
}

// ---------------- fused transpose of both conv weights (to bf16 planes) ----------------
__global__ void k_tr_both(const float* __restrict__ c1w, const float* __restrict__ c2w) {
  const int c1 = blockIdx.x < 9;
  const float* __restrict__ src = c1 ? c1w : c2w;
  const int M = 256;
  const int N = c1 ? 270 : 2304;
  const int bx = c1 ? blockIdx.x : blockIdx.x - 9;
  __shared__ float t[32][33];
  const int tx = threadIdx.x;
  const int x = bx * 32 + tx;
  const int y0 = blockIdx.y * 32;
  for (int j = threadIdx.y; j < 32; j += 8) {
    int y = y0 + j;
    if (x < N && y < M) t[j][tx] = src[(size_t)y * N + x];
  }
  __syncthreads();
  const int xo = y0 + tx;   // co (M dim)
  const int yo0 = bx * 32;
  for (int j = threadIdx.y; j < 32; j += 8) {
    int yo = yo0 + j;       // k (N dim)
    if (xo < M) {
      if (c1) {
        if (yo < K1P) {
          float v = (yo < 270) ? t[tx][j] : 0.f;
          __nv_bfloat16 bh = __float2bfloat16(v);
          float vh = __bfloat162float(bh);
          __nv_bfloat16 bl = __float2bfloat16(v - vh);
          size_t idx = (size_t)(yo >> 1) * 512 + 2 * xo + (yo & 1);
          g_w1ph[idx] = __bfloat16_as_ushort(bh);
          g_w1pl[idx] = __bfloat16_as_ushort(bl);
        }
      } else if (yo < N) {
        float v = t[tx][j];
        __nv_bfloat16 bh = __float2bfloat16(v);
        float vh = __bfloat162float(bh);
        __nv_bfloat16 bl = __float2bfloat16(v - vh);
        size_t idx = (size_t)(yo >> 1) * 512 + 2 * xo + (yo & 1);
        g_w2ph[idx] = __bfloat16_as_ushort(bh);
        g_w2pl[idx] = __bfloat16_as_ushort(bl);
      }
    }
  }
}

// ---------------- caps_w transpose + route-GEMM weight planes ----------------
__global__ void k_transpose_w(const float* __restrict__ cw) {
  int idx = blockIdx.x * 256 + threadIdx.x;       // over 16*3872*128
  if (idx >= NCLS * NCAPS * 128) return;
  int o = idx / (NCAPS * 128);
  int rem = idx - o * (NCAPS * 128);
  int n = rem >> 7;
  int ij = rem & 127;
  float v = cw[idx];
  g_wt[n * 2048 + o * 128 + ij] = v;
  int i = ij >> 3, j = ij & 7;
  int nj = n * 8 + j, oi = o * 16 + i;
  __nv_bfloat16 bh = __float2bfloat16(v);
  float vh = __bfloat162float(bh);
  __nv_bfloat16 bl = __float2bfloat16(v - vh);
  size_t widx = (size_t)(nj >> 1) * 512 + 2 * oi + (nj & 1);
  g_wrph[widx] = __bfloat16_as_ushort(bh);
  g_wrpl[widx] = __bfloat16_as_ushort(bl);
}

// ---------------- shared MMA helper ----------------
__device__ __forceinline__ void mma16(float* c, const unsigned* a, const unsigned* b) {
  asm volatile(
      "mma.sync.aligned.m16n8k16.row.col.f32.bf16.bf16.f32 "
      "{%0,%1,%2,%3},{%4,%5,%6,%7},{%8,%9},{%0,%1,%2,%3};"
      : "+f"(c[0]), "+f"(c[1]), "+f"(c[2]), "+f"(c[3])
      : "r"(a[0]), "r"(a[1]), "r"(a[2]), "r"(a[3]), "r"(b[0]), "r"(b[1]));
}

// ---------------- conv1 as implicit GEMM (3-term bf16 k16) ----------------
__global__ void __launch_bounds__(256, 2) k_conv1_mma(const float* __restrict__ b1c) {
  __shared__ __align__(16) unsigned As_h[2][8 * 136];
  __shared__ __align__(16) unsigned As_l[2][8 * 136];
  __shared__ __align__(16) unsigned Bs_h[2][8 * 136];
  __shared__ __align__(16) unsigned Bs_l[2][8 * 136];
  __shared__ int offs_s[K1P];
  __shared__ int posoff_s[128];
  const int cbt = blockIdx.x, pt = blockIdx.y, b = blockIdx.z;
  const int tid = threadIdx.x;
  for (int i = tid; i < K1P; i += 256) {
    if (i < 270) {
      int ci = i / 9, r = i - 9 * ci;
      int kh = r / 3, kw = r - 3 * kh;
      offs_s[i] = ci * (H0 * W0) + kh * W0 + kw;
    } else {
      offs_s[i] = 0;
    }
  }
  if (tid < 128) {
    int p = pt * 128 + tid;
    posoff_s[tid] = (p < P1) ? (p / W1) * W0 + (p - (p / W1) * W1) : 0;
  }
  const int lane = tid & 31, gid = lane >> 2, tg = lane & 3;
  const int w = tid >> 5, wm = w >> 2, wn = w & 3;
  const int cb = wm * 64, pb = wn * 32;
  float acc[4][4][4];
#pragma unroll
  for (int mt = 0; mt < 4; mt++)
#pragma unroll
    for (int nt = 0; nt < 4; nt++)
#pragma unroll
      for (int q = 0; q < 4; q++) acc[mt][nt][q] = 0.f;
  const unsigned* __restrict__ xpk = g_xpk + (size_t)b * XSZ;
  const unsigned* __restrict__ wAh = (const unsigned*)g_w1ph;
  const unsigned* __restrict__ wAl = (const unsigned*)g_w1pl;
  const int skk0 = tid >> 7, scol = tid & 127;
  const int coA = cbt * 128 + scol;
  const bool pvalid = (pt * 128 + scol) < P1;
  unsigned pa_h[4], pa_l[4], pb_h[4], pb_l[4];
#define PREFETCH(kc_)                                                         \
  {                                                                           \
    _Pragma("unroll") for (int t = 0; t < 4; t++) {                           \
      int p = skk0 + 2 * t;                                                   \
      int k2g = (kc_) * 8 + p;                                                \
      pa_h[t] = wAh[(size_t)k2g * 256 + coA];                                 \
      pa_l[t] = wAl[(size_t)k2g * 256 + coA];                                 \
      unsigned e0 = 0, e1 = 0;                                                \
      if (pvalid) {                                                           \
        int po = posoff_s[scol];                                              \
        int kg = (kc_) * 16 + 2 * p;                                          \
        e0 = xpk[offs_s[kg] + po];                                            \
        e1 = xpk[offs_s[kg + 1] + po];                                        \
      }                                                                       \
      pb_h[t] = __byte_perm(e0, e1, 0x5410);                                  \
      pb_l[t] = __byte_perm(e0, e1, 0x7632);                                  \
    }                                                                         \
  }
#define STAGE(buf_)                                                           \
  {                                                                           \
    _Pragma("unroll") for (int t = 0; t < 4; t++) {                           \
      int p = skk0 + 2 * t;                                                   \
      As_h[buf_][p * 136 + scol] = pa_h[t];                                   \
      As_l[buf_][p * 136 + scol] = pa_l[t];                                   \
      Bs_h[buf_][p * 136 + scol] = pb_h[t];                                   \
      Bs_l[buf_][p * 136 + scol] = pb_l[t];                                   \
    }                                                                         \
  }
  __syncthreads();
  PREFETCH(0);
  STAGE(0);
  __syncthreads();
  for (int kc = 0; kc < NKC1; kc++) {
    if (kc + 1 < NKC1) PREFETCH(kc + 1);
    const unsigned* Ah = As_h[kc & 1];
    const unsigned* Al = As_l[kc & 1];
    const unsigned* Bh = Bs_h[kc & 1];
    const unsigned* Bl = Bs_l[kc & 1];
    unsigned bh[4][2], bl[4][2];
#pragma unroll
    for (int nt = 0; nt < 4; nt++) {
      int col = pb + nt * 8 + gid;
      bh[nt][0] = Bh[tg * 136 + col];
      bh[nt][1] = Bh[(tg + 4) * 136 + col];
      bl[nt][0] = Bl[tg * 136 + col];
      bl[nt][1] = Bl[(tg + 4) * 136 + col];
    }
#pragma unroll
    for (int mt = 0; mt < 4; mt++) {
      int row = cb + mt * 16 + gid;
      unsigned ah[4] = {Ah[tg * 136 + row], Ah[tg * 136 + row + 8],
                        Ah[(tg + 4) * 136 + row], Ah[(tg + 4) * 136 + row + 8]};
      unsigned al[4] = {Al[tg * 136 + row], Al[tg * 136 + row + 8],
                        Al[(tg + 4) * 136 + row], Al[(tg + 4) * 136 + row + 8]};
#pragma unroll
      for (int nt = 0; nt < 4; nt++) {
        mma16(acc[mt][nt], ah, bh[nt]);
        mma16(acc[mt][nt], ah, bl[nt]);
        mma16(acc[mt][nt], al, bh[nt]);
      }
    }
    if (kc + 1 < NKC1) STAGE((kc + 1) & 1);
    __syncthreads();
  }
#pragma unroll
  for (int mt = 0; mt < 4; mt++) {
    int co = cbt * 128 + cb + mt * 16 + gid;
    float bs0 = b1c[co], bs1 = b1c[co + 8];
#pragma unroll
    for (int nt = 0; nt < 4; nt++) {
      int pl = pb + nt * 8 + 2 * tg;
      int pg = pt * 128 + pl;
      if (pg < P1) {
        g_h[((size_t)b * C1 + co) * P1 + pg] = acc[mt][nt][0] + bs0;
        g_h[((size_t)b * C1 + co + 8) * P1 + pg] = acc[mt][nt][2] + bs1;
      }
      if (pg + 1 < P1 && pl + 1 < 128) {
        g_h[((size_t)b * C1 + co) * P1 + pg + 1] = acc[mt][nt][1] + bs0;
        g_h[((size_t)b * C1 + co + 8) * P1 + pg + 1] = acc[mt][nt][3] + bs1;
      }
    }
  }
#undef PREFETCH
#undef STAGE
}

// ---------------- batchnorm stats + fused BN+relu+bf16-split pack ----------------
__global__ void k_bnstats(const float* __restrict__ gamma, const float* __restrict__ beta) {
  const int c = blockIdx.x, tid = threadIdx.x;
  float s = 0.f, s2 = 0.f;
  for (int i = tid; i < NB * P1; i += 256) {
    int b = i / P1, p = i - (i / P1) * P1;
    float v = g_h[((size_t)b * C1 + c) * P1 + p];
    s += v; s2 += v * v;
  }
  __shared__ float rs[256], rq[256];
  __shared__ float ssc, ssh;
  rs[tid] = s; rq[tid] = s2;
  __syncthreads();
  for (int st = 128; st > 0; st >>= 1) {
    if (tid < st) { rs[tid] += rs[tid + st]; rq[tid] += rq[tid + st]; }
    __syncthreads();
  }
  if (tid == 0) {
    const float inv_n = 1.f / (float)(NB * P1);
    float mean = rs[0] * inv_n;
    float var = fmaxf(rq[0] * inv_n - mean * mean, 0.f);
    float sc = gamma[c] * rsqrtf(var + 1e-5f);
    ssc = sc;
    ssh = beta[c] - mean * sc;
  }
  __syncthreads();
  const float sc = ssc, sh = ssh;
  for (int i = tid; i < NB * P1; i += 256) {
    int b = i / P1, p = i - (i / P1) * P1;
    size_t idx = ((size_t)b * C1 + c) * P1 + p;
    float v = g_h[idx] * sc + sh;
    v = v > 0.f ? v : 0.f;
    g_hpk[idx] = packf(v);
  }
}

// ---------------- conv2 as implicit GEMM (R14 proven config) ----------------
__global__ void __launch_bounds__(256, 2) k_conv2_mma(const float* __restrict__ b2) {
  __shared__ __align__(16) unsigned As_h[2][8 * 136];
  __shared__ __align__(16) unsigned As_l[2][8 * 136];
  __shared__ __align__(16) unsigned Bs_h[2][8 * 136];
  __shared__ __align__(16) unsigned Bs_l[2][8 * 136];
  __shared__ int offs_s[K2];
  __shared__ int posoff_s[128];
  const int b = blockIdx.y, cbt = blockIdx.x;
  const int tid = threadIdx.x;
  for (int i = tid; i < K2; i += 256) {
    int ci = i / 9, r = i - 9 * ci;
    int kh = r / 3, kw = r - 3 * kh;
    offs_s[i] = ci * P1 + kh * W1 + kw;
  }
  if (tid < 128) posoff_s[tid] = (tid / 11) * W1 + (tid - (tid / 11) * 11);
  const int lane = tid & 31, gid = lane >> 2, tg = lane & 3;
  const int w = tid >> 5, wm = w >> 2, wn = w & 3;
  const int cb = wm * 64, pb = wn * 32;
  float acc[4][4][4];
#pragma unroll
  for (int mt = 0; mt < 4; mt++)
#pragma unroll
    for (int nt = 0; nt < 4; nt++)
#pragma unroll
      for (int q = 0; q < 4; q++) acc[mt][nt][q] = 0.f;
  const unsigned* __restrict__ hpk = g_hpk + (size_t)b * C1 * P1;
  const unsigned* __restrict__ wAh = (const unsigned*)g_w2ph;
  const unsigned* __restrict__ wAl = (const unsigned*)g_w2pl;
  const int skk0 = tid >> 7, scol = tid & 127;
  const int coA = cbt * 128 + scol;
  unsigned pa_h[4], pa_l[4], pb_h[4], pb_l[4];
#define PREFETCH(kc_)                                                         \
  {                                                                           \
    _Pragma("unroll") for (int t = 0; t < 4; t++) {                           \
      int p = skk0 + 2 * t;                                                   \
      int k2g = (kc_) * 8 + p;                                                \
      pa_h[t] = wAh[(size_t)k2g * 256 + coA];                                 \
      pa_l[t] = wAl[(size_t)k2g * 256 + coA];                                 \
      unsigned e0 = 0, e1 = 0;                                                \
      if (scol < 121) {                                                       \
        int po = posoff_s[scol];                                              \
        int kg = (kc_) * KC + 2 * p;                                          \
        e0 = hpk[offs_s[kg] + po];                                            \
        e1 = hpk[offs_s[kg + 1] + po];                                        \
      }                                                                       \
      pb_h[t] = __byte_perm(e0, e1, 0x5410);                                  \
      pb_l[t] = __byte_perm(e0, e1, 0x7632);                                  \
    }                                                                         \
  }
#define STAGE(buf_)                                                           \
  {                                                                           \
    _Pragma("unroll") for (int t = 0; t < 4; t++) {                           \
      int p = skk0 + 2 * t;                                                   \
      As_h[buf_][p * 136 + scol] = pa_h[t];                                   \
      As_l[buf_][p * 136 + scol] = pa_l[t];                                   \
      Bs_h[buf_][p * 136 + scol] = pb_h[t];                                   \
      Bs_l[buf_][p * 136 + scol] = pb_l[t];                                   \
    }                                                                         \
  }
  __syncthreads();
  PREFETCH(0);
  STAGE(0);
  __syncthreads();
  for (int kc = 0; kc < NKC; kc++) {
    if (kc + 1 < NKC) PREFETCH(kc + 1);
    const unsigned* Ah = As_h[kc & 1];
    const unsigned* Al = As_l[kc & 1];
    const unsigned* Bh = Bs_h[kc & 1];
    const unsigned* Bl = Bs_l[kc & 1];
    unsigned bh[4][2], bl[4][2];
#pragma unroll
    for (int nt = 0; nt < 4; nt++) {
      int col = pb + nt * 8 + gid;
      bh[nt][0] = Bh[tg * 136 + col];
      bh[nt][1] = Bh[(tg + 4) * 136 + col];
      bl[nt][0] = Bl[tg * 136 + col];
      bl[nt][1] = Bl[(tg + 4) * 136 + col];
    }
#pragma unroll
    for (int mt = 0; mt < 4; mt++) {
      int row = cb + mt * 16 + gid;
      unsigned ah[4] = {Ah[tg * 136 + row], Ah[tg * 136 + row + 8],
                        Ah[(tg + 4) * 136 + row], Ah[(tg + 4) * 136 + row + 8]};
      unsigned al[4] = {Al[tg * 136 + row], Al[tg * 136 + row + 8],
                        Al[(tg + 4) * 136 + row], Al[(tg + 4) * 136 + row + 8]};
#pragma unroll
      for (int nt = 0; nt < 4; nt++) {
        mma16(acc[mt][nt], ah, bh[nt]);
        mma16(acc[mt][nt], ah, bl[nt]);
        mma16(acc[mt][nt], al, bh[nt]);
      }
    }
    if (kc + 1 < NKC) STAGE((kc + 1) & 1);
    __syncthreads();
  }
  float* outb = g_pbuf + (size_t)b * NFLAT;
#pragma unroll
  for (int mt = 0; mt < 4; mt++) {
    int co = cbt * 128 + cb + mt * 16 + gid;
    float bs0 = b2[co], bs1 = b2[co + 8];
#pragma unroll
    for (int nt = 0; nt < 4; nt++) {
      int p = pb + nt * 8 + 2 * tg;
      if (p < P2) {
        outb[co * P2 + p] = acc[mt][nt][0] + bs0;
        outb[(co + 8) * P2 + p] = acc[mt][nt][2] + bs1;
      }
      if (p + 1 < P2) {
        outb[co * P2 + p + 1] = acc[mt][nt][1] + bs0;
        outb[(co + 8) * P2 + p + 1] = acc[mt][nt][3] + bs1;
      }
    }
  }
#undef PREFETCH
#undef STAGE
}

// ---------------- primary capsule squash + transpose + bf16 pack ----------------
__global__ void k_squash(void) {
  const int n = blockIdx.x, b = threadIdx.x;
  const float4* src = (const float4*)(g_pbuf + (size_t)b * NFLAT + n * IND);
  float4 a0 = src[0], a1 = src[1];
  float v[8] = {a0.x, a0.y, a0.z, a0.w, a1.x, a1.y, a1.z, a1.w};
  float ss = 0.f;
#pragma unroll
  for (int j = 0; j < 8; j++) ss += v[j] * v[j];
  float nrm = sqrtf(ss);
  float sc = ss / (1.f + ss) / (nrm + 1e-8f);
#pragma unroll
  for (int j = 0; j < 8; j++) {
    float cv = v[j] * sc;
    size_t idx = ((size_t)n * IND + j) * NB + b;
    g_caps[idx] = cv;
    g_caps_pk[idx] = packf(cv);
  }
}

// ---------------- routing pass0 as GEMM (R14 proven config) ----------------
__global__ void __launch_bounds__(256, 2) k_route0_mma() {
  __shared__ __align__(16) unsigned As_h[2][8 * 136];
  __shared__ __align__(16) unsigned As_l[2][8 * 136];
  __shared__ __align__(16) unsigned Bs_h[2][8 * 136];
  __shared__ __align__(16) unsigned Bs_l[2][8 * 136];
  const int half = blockIdx.x, split = blockIdx.y;
  const int tid = threadIdx.x;
  const int lane = tid & 31, gid = lane >> 2, tg = lane & 3;
  const int w = tid >> 5, wm = w >> 2, wn = w & 3;
  const int cb = wm * 64, pb = wn * 32;
  float acc[4][4][4];
#pragma unroll
  for (int mt = 0; mt < 4; mt++)
#pragma unroll
    for (int nt = 0; nt < 4; nt++)
#pragma unroll
      for (int q = 0; q < 4; q++) acc[mt][nt][q] = 0.f;
  const unsigned* __restrict__ wAh = (const unsigned*)g_wrph;
  const unsigned* __restrict__ wAl = (const unsigned*)g_wrpl;
  const int skk0 = tid >> 7, scol = tid & 127;
  const int oiA = half * 128 + scol;
  const int kp0 = split * (KR_SPLIT / 2);
  unsigned pa_h[4], pa_l[4], pb_h[4], pb_l[4];
#define PREFETCH(kc_)                                                         \
  {                                                                           \
    _Pragma("unroll") for (int t = 0; t < 4; t++) {                           \
      int p = skk0 + 2 * t;                                                   \
      int pg = kp0 + (kc_) * 8 + p;                                           \
      pa_h[t] = wAh[(size_t)pg * 256 + oiA];                                  \
      pa_l[t] = wAl[(size_t)pg * 256 + oiA];                                  \
      unsigned e0 = g_caps_pk[(size_t)(2 * pg) * NB + scol];                  \
      unsigned e1 = g_caps_pk[(size_t)(2 * pg + 1) * NB + scol];              \
      pb_h[t] = __byte_perm(e0, e1, 0x5410);                                  \
      pb_l[t] = __byte_perm(e0, e1, 0x7632);                                  \
    }                                                                         \
  }
#define STAGE(buf_)                                                           \
  {                                                                           \
    _Pragma("unroll") for (int t = 0; t < 4; t++) {                           \
      int p = skk0 + 2 * t;                                                   \
      As_h[buf_][p * 136 + scol] = pa_h[t];                                   \
      As_l[buf_][p * 136 + scol] = pa_l[t];                                   \
      Bs_h[buf_][p * 136 + scol] = pb_h[t];                                   \
      Bs_l[buf_][p * 136 + scol] = pb_l[t];                                   \
    }                                                                         \
  }
  PREFETCH(0);
  STAGE(0);
  __syncthreads();
  const int NCH = KR_SPLIT / 16;   // 22
  for (int kc = 0; kc < NCH; kc++) {
    if (kc + 1 < NCH) PREFETCH(kc + 1);
    const unsigned* Ah = As_h[kc & 1];
    const unsigned* Al = As_l[kc & 1];
    const unsigned* Bh = Bs_h[kc & 1];
    const unsigned* Bl = Bs_l[kc & 1];
    unsigned bh[4][2], bl[4][2];
#pragma unroll
    for (int nt = 0; nt < 4; nt++) {
      int col = pb + nt * 8 + gid;
      bh[nt][0] = Bh[tg * 136 + col];
      bh[nt][1] = Bh[(tg + 4) * 136 + col];
      bl[nt][0] = Bl[tg * 136 + col];
      bl[nt][1] = Bl[(tg + 4) * 136 + col];
    }
#pragma unroll
    for (int mt = 0; mt < 4; mt++) {
      int row = cb + mt * 16 + gid;
      unsigned ah[4] = {Ah[tg * 136 + row], Ah[tg * 136 + row + 8],
                        Ah[(tg + 4) * 136 + row], Ah[(tg + 4) * 136 + row + 8]};
      unsigned al[4] = {Al[tg * 136 + row], Al[tg * 136 + row + 8],
                        Al[(tg + 4) * 136 + row], Al[(tg + 4) * 136 + row + 8]};
#pragma unroll
      for (int nt = 0; nt < 4; nt++) {
        mma16(acc[mt][nt], ah, bh[nt]);
        mma16(acc[mt][nt], ah, bl[nt]);
        mma16(acc[mt][nt], al, bh[nt]);
      }
    }
    if (kc + 1 < NCH) STAGE((kc + 1) & 1);
    __syncthreads();
  }
  float* dst = g_spart + (size_t)split * NB * 256 + half * 128;
#pragma unroll
  for (int mt = 0; mt < 4; mt++) {
    int row = cb + mt * 16 + gid;     // oi local
#pragma unroll
    for (int nt = 0; nt < 4; nt++) {
      int col = pb + nt * 8 + 2 * tg; // b
      dst[(size_t)col * 256 + row] = acc[mt][nt][0] * 0.0625f;
      dst[(size_t)(col + 1) * 256 + row] = acc[mt][nt][1] * 0.0625f;
      dst[(size_t)col * 256 + row + 8] = acc[mt][nt][2] * 0.0625f;
      dst[(size_t)(col + 1) * 256 + row + 8] = acc[mt][nt][3] * 0.0625f;
    }
  }
#undef PREFETCH
#undef STAGE
}

// ---------------- routing pass 1/2 (v4: deduplicated softmax) ----------------
// v2 structure; softmax split across the 8 threads sharing a b (2 o's each):
// 2 exps/thread/n instead of 16 (8x MUFU reduction), shared via smem.
__global__ void __launch_bounds__(256) k_route1() {
  __shared__ __align__(16) float ws[2 * 2048];
  __shared__ float red[256 * 9];       // logit partials, pitch 9
  __shared__ float mxb[256];           // per-thread max of its 2 logits
  __shared__ float dnb[256];           // per-thread partial denominator
  __shared__ float ebuf[512];          // per-thread 2 exps
  const int tid = threadIdx.x;
  const int bl = tid & 31;
  const int iq = (tid >> 5) & 3;
  const int oh = tid >> 7;
  const int b = blockIdx.y * 32 + bl;
  float outa[32];
#pragma unroll
  for (int o8 = 0; o8 < 8; o8++)
#pragma unroll
    for (int ii = 0; ii < 4; ii++)
      outa[o8 * 4 + ii] = g_out_sum[b * 256 + (oh * 8 + o8) * 16 + iq * 4 + ii];
  float s[32];
#pragma unroll
  for (int t = 0; t < 32; t++) s[t] = 0.f;
  const int n0 = blockIdx.x * NPC;
  float4 pre0, pre1;
  {
    const float4* sr = (const float4*)(g_wt + (size_t)n0 * 2048);
    pre0 = sr[tid]; pre1 = sr[tid + 256];
  }
  int cur = 0;
  for (int nn = 0; nn < NPC; nn++) {
    const int n = n0 + nn;
    float4* wbuf = (float4*)(ws + cur * 2048);
    wbuf[tid] = pre0; wbuf[tid + 256] = pre1;
    __syncthreads();
    if (nn + 1 < NPC) {
      const float4* sr = (const float4*)(g_wt + (size_t)(n + 1) * 2048);
      pre0 = sr[tid]; pre1 = sr[tid + 256];
    }
    float cj[8];
#pragma unroll
    for (int j = 0; j < 8; j++) cj[j] = g_caps[((size_t)n * 8 + j) * NB + b];
    const float* wb = ws + cur * 2048 + oh * 1024 + iq * 32;
    float v[32];
#pragma unroll
    for (int o8 = 0; o8 < 8; o8++) {
      const float4* w4 = (const float4*)(wb + o8 * 128);
#pragma unroll
      for (int ii = 0; ii < 4; ii++) {
        float4 a = w4[2 * ii], d = w4[2 * ii + 1];
        v[o8 * 4 + ii] = a.x * cj[0] + a.y * cj[1] + a.z * cj[2] + a.w * cj[3]
                       + d.x * cj[4] + d.y * cj[5] + d.z * cj[6] + d.w * cj[7];
      }
    }
#pragma unroll
    for (int o8 = 0; o8 < 8; o8++) {
      float lg = outa[o8 * 4] * v[o8 * 4] + outa[o8 * 4 + 1] * v[o8 * 4 + 1]
               + outa[o8 * 4 + 2] * v[o8 * 4 + 2] + outa[o8 * 4 + 3] * v[o8 * 4 + 3];
      red[tid * 9 + o8] = lg;
    }
    __syncthreads();
    // this thread handles o8 = iq*2, iq*2+1 of its oh half
    float lg2[2];
#pragma unroll
    for (int r = 0; r < 2; r++) {
      int o8r = iq * 2 + r;
      lg2[r] = red[((oh * 4 + 0) * 32 + bl) * 9 + o8r]
             + red[((oh * 4 + 1) * 32 + bl) * 9 + o8r]
             + red[((oh * 4 + 2) * 32 + bl) * 9 + o8r]
             + red[((oh * 4 + 3) * 32 + bl) * 9 + o8r];
    }
    mxb[tid] = fmaxf(lg2[0], lg2[1]);
    __syncthreads();
    float gm = mxb[bl];
#pragma unroll
    for (int g = 1; g < 8; g++) gm = fmaxf(gm, mxb[g * 32 + bl]);
    float e0 = __expf(lg2[0] - gm);
    float e1 = __expf(lg2[1] - gm);
    ebuf[tid * 2] = e0;
    ebuf[tid * 2 + 1] = e1;
    dnb[tid] = e0 + e1;
    __syncthreads();
    float den = dnb[bl];
#pragma unroll
    for (int g = 1; g < 8; g++) den += dnb[g * 32 + bl];
    float inv = 1.f / den;
    float c[8];
#pragma unroll
    for (int q = 0; q < 4; q++) {
      int src = (oh * 128 + q * 32 + bl) * 2;
      c[q * 2] = ebuf[src] * inv;
      c[q * 2 + 1] = ebuf[src + 1] * inv;
    }
#pragma unroll
    for (int o8 = 0; o8 < 8; o8++)
#pragma unroll
      for (int ii = 0; ii < 4; ii++) s[o8 * 4 + ii] += c[o8] * v[o8 * 4 + ii];
    cur ^= 1;
  }
  float* dst = g_spart + ((size_t)blockIdx.x * NB + b) * 256;
#pragma unroll
  for (int o8 = 0; o8 < 8; o8++)
#pragma unroll
    for (int ii = 0; ii < 4; ii++)
      dst[(oh * 8 + o8) * 16 + iq * 4 + ii] = s[o8 * 4 + ii];
}

// ---------------- reduce partials + squash (+ final: length & mask) ----------------
__global__ void k_reduce_squash(const float* __restrict__ y, float* __restrict__ d_out,
                                int first, int final_) {
  const int b = blockIdx.x, tid = threadIdx.x;
  float v = 0.f;
  for (int ch = 0; ch < NCHUNKS; ch++)
    v += g_spart[((size_t)ch * NB + b) * 256 + tid];
  float ss = v * v;
#pragma unroll
  for (int m = 1; m < 16; m <<= 1) ss += __shfl_xor_sync(0xffffffffu, ss, m);
  float nrm = sqrtf(ss);
  float sc = ss / (1.f + ss) / (nrm + 1e-8f);
  float ov = v * sc;
  if (!final_) {
    if (first) g_out_sum[b * 256 + tid] = ov;
    else g_out_sum[b * 256 + tid] += ov;
  } else {
    int o = tid >> 4, i = tid & 15;
    if (i == 0) d_out[b * NCLS + o] = sc * nrm;
    g_masked[b * 256 + tid] = ov * y[b * NCLS + o];
  }
}

// ---------------- decoder MLP: dec1+dec2 fused ----------------
__global__ void k_dec12(const float* __restrict__ w1, const float* __restrict__ b1,
                        const float* __restrict__ w2, const float* __restrict__ b2) {
  __shared__ float m[256];
  __shared__ float r1s[DEC1];
  const int b = blockIdx.x, tid = threadIdx.x;    // 328 threads
  if (tid < 256) m[tid] = g_masked[b * 256 + tid];
  __syncthreads();
  {
    float acc = b1[tid];
    for (int k = 0; k < 256; k++) acc += m[k] * w1[k * DEC1 + tid];
    r1s[tid] = 1.f / (1.f + __expf(-acc));
  }
  __syncthreads();
  if (tid < DEC2) {
    float acc = b2[tid];
    for (int k = 0; k < DEC1; k++) acc += r1s[k] * w2[k * DEC2 + tid];
    g_r2[b * DEC2 + tid] = 1.f / (1.f + __expf(-acc));
  }
}

__global__ void k_dec3(const float* __restrict__ w3, const float* __restrict__ b3,
                       float* __restrict__ d_out) {
  __shared__ float m[8 * DEC2];
  const int bq = blockIdx.y * 8;
  const int tid = threadIdx.x;
  const int j = blockIdx.x * 256 + tid;
  for (int i = tid; i < 8 * DEC2; i += 256)
    m[i] = g_r2[(bq + i / DEC2) * DEC2 + (i % DEC2)];
  __syncthreads();
  if (j >= DEC3) return;
  float acc[8];
  float bv = b3[j];
#pragma unroll
  for (int q = 0; q < 8; q++) acc[q] = bv;
  for (int k = 0; k < DEC2; k++) {
    float w = w3[(size_t)k * DEC3 + j];
#pragma unroll
    for (int q = 0; q < 8; q++) acc[q] += m[q * DEC2 + k] * w;
  }
#pragma unroll
  for (int q = 0; q < 8; q++)
    d_out[NB * NCLS + (size_t)(bq + q) * DEC3 + j] = acc[q];
}

// ---------------- launcher ----------------
extern "C" void kernel_launch(void* const* d_in, const int* in_sizes, int n_in,
                              void* d_out, int out_size) {
  const float* x   = (const float*)d_in[0];
  const float* y   = (const float*)d_in[1];
  const float* c1w = (const float*)d_in[2];
  const float* c1b = (const float*)d_in[3];
  const float* bng = (const float*)d_in[4];
  const float* bnb = (const float*)d_in[5];
  const float* c2w = (const float*)d_in[6];
  const float* c2b = (const float*)d_in[7];
  const float* cpw = (const float*)d_in[8];
  const float* dw1 = (const float*)d_in[9];
  const float* db1 = (const float*)d_in[10];
  const float* dw2 = (const float*)d_in[11];
  const float* db2 = (const float*)d_in[12];
  const float* dw3 = (const float*)d_in[13];
  const float* db3 = (const float*)d_in[14];
  float* out = (float*)d_out;
  (void)in_sizes; (void)n_in; (void)out_size;

  k_packx<<<(NB * XSZ + 255) / 256, 256>>>(x);
  k_tr_both<<<dim3(81, 8), dim3(32, 8)>>>(c1w, c2w);
  k_transpose_w<<<(NCLS * NCAPS * 128 + 255) / 256, 256>>>(cpw);
  k_conv1_mma<<<dim3(2, 2, NB), 256>>>(c1b);   // launch #4 -> ncu capture slot
  k_bnstats<<<C1, 256>>>(bng, bnb);
  k_conv2_mma<<<dim3(2, NB), 256>>>(c2b);
  k_squash<<<NCAPS, NB>>>();

  k_route0_mma<<<dim3(2, NCHUNKS), 256>>>();
  k_reduce_squash<<<NB, 256>>>(y, out, 1, 0);
  k_route1<<<dim3(NCHUNKS, 4), 256>>>();
  k_reduce_squash<<<NB, 256>>>(y, out, 0, 0);
  k_route1<<<dim3(NCHUNKS, 4), 256>>>();
  k_reduce_squash<<<NB, 256>>>(y, out, 0, 1);

  k_dec12<<<NB, DEC1>>>(dw1, db1, dw2, db2);
  k_dec3<<<dim3(27, 16), 256>>>(dw3, db3, out);
}